// round 6
// baseline (speedup 1.0000x reference)
#include <cuda_runtime.h>
#include <cuda_bf16.h>
#include <cstdint>
#include <cstddef>

#define SEQ 4096
#define DMODEL 1024

// ---------------------------------------------------------------------------
// Scratch (allocation-free rule: device globals)
// ---------------------------------------------------------------------------
__device__ __align__(128) float g_Q[(size_t)SEQ * DMODEL];
__device__ __align__(128) float g_K[(size_t)SEQ * DMODEL];
__device__ __align__(128) float g_V[(size_t)SEQ * DMODEL];
__device__ __align__(128) float g_S[(size_t)SEQ * SEQ];

__device__ __align__(128) __nv_bfloat16 g_Xh[(size_t)SEQ * DMODEL];
__device__ __align__(128) __nv_bfloat16 g_Xl[(size_t)SEQ * DMODEL];
__device__ __align__(128) __nv_bfloat16 g_Wqh[(size_t)DMODEL * DMODEL];
__device__ __align__(128) __nv_bfloat16 g_Wql[(size_t)DMODEL * DMODEL];
__device__ __align__(128) __nv_bfloat16 g_Wkh[(size_t)DMODEL * DMODEL];
__device__ __align__(128) __nv_bfloat16 g_Wkl[(size_t)DMODEL * DMODEL];
__device__ __align__(128) __nv_bfloat16 g_Wvh[(size_t)DMODEL * DMODEL];
__device__ __align__(128) __nv_bfloat16 g_Wvl[(size_t)DMODEL * DMODEL];
__device__ __align__(128) __nv_bfloat16 g_Qh[(size_t)SEQ * DMODEL];
__device__ __align__(128) __nv_bfloat16 g_Ql[(size_t)SEQ * DMODEL];
__device__ __align__(128) __nv_bfloat16 g_Kh[(size_t)SEQ * DMODEL];
__device__ __align__(128) __nv_bfloat16 g_Kl[(size_t)SEQ * DMODEL];
__device__ __align__(128) __nv_bfloat16 g_Vth[(size_t)DMODEL * SEQ];
__device__ __align__(128) __nv_bfloat16 g_Vtl[(size_t)DMODEL * SEQ];
__device__ __align__(128) __nv_bfloat16 g_Ph[(size_t)SEQ * SEQ];
__device__ __align__(128) __nv_bfloat16 g_Pl[(size_t)SEQ * SEQ];

// ---------------------------------------------------------------------------
// PTX helpers (base PTX only)
// ---------------------------------------------------------------------------
__device__ __forceinline__ uint32_t smem_u32(const void* p) {
    uint32_t a;
    asm("{ .reg .u64 t; cvta.to.shared.u64 t, %1; cvt.u32.u64 %0, t; }"
        : "=r"(a) : "l"(p));
    return a;
}
#define CP_ASYNC16(dst, src) \
    asm volatile("cp.async.cg.shared.global [%0], [%1], 16;" \
                 :: "r"(dst), "l"(src) : "memory")
#define CP_COMMIT() asm volatile("cp.async.commit_group;" ::: "memory")
#define CP_WAIT1()  asm volatile("cp.async.wait_group 1;" ::: "memory")

#define LDSM_X4(r0, r1, r2, r3, addr) \
    asm volatile("ldmatrix.sync.aligned.m8n8.x4.shared.b16 {%0,%1,%2,%3}, [%4];" \
                 : "=r"(r0), "=r"(r1), "=r"(r2), "=r"(r3) : "r"(addr))

#define MMA_BF16(d, a, b) \
    asm volatile("mma.sync.aligned.m16n8k16.row.col.f32.bf16.bf16.f32 " \
                 "{%0,%1,%2,%3}, {%4,%5,%6,%7}, {%8,%9}, {%0,%1,%2,%3};" \
                 : "+f"((d)[0]), "+f"((d)[1]), "+f"((d)[2]), "+f"((d)[3]) \
                 : "r"((a)[0]), "r"((a)[1]), "r"((a)[2]), "r"((a)[3]), \
                   "r"((b)[0]), "r"((b)[1]))

// ---------------------------------------------------------------------------
// HMMA GEMM:  C[M, Nglob] = (Ah+Al)[M, Kd] @ (Bh+Bl)[Nglob, Kd]^T
// bf16 split, fp32 accum; 3 MMA passes (hh, hl, lh).
// CTA tile 256x128x64, 512 threads, 16 warps (4x4), warp tile 64x32.
// 2-stage cp.async pipeline; SW128-XOR smem layout.
// ---------------------------------------------------------------------------
#define BK 64
#define A_TILE_B 32768          // 256 x 64 bf16
#define B_TILE_B 16384          // 128 x 64 bf16
#define STAGE_B  (2 * A_TILE_B + 2 * B_TILE_B)   // Ah|Al|Bh|Bl = 96KB
#define NSTAGE   2
#define GEMM_SMEM (NSTAGE * STAGE_B)             // 196608

__device__ __forceinline__ uint32_t sw_off(int row, int chunk) {
    uint32_t off = (uint32_t)(row * 128 + chunk * 16);
    return off ^ ((off >> 3) & 0x70);
}

__global__ __launch_bounds__(512, 1) void hmma_gemm_nt(
    const __nv_bfloat16* __restrict__ Ah, const __nv_bfloat16* __restrict__ Al,
    const __nv_bfloat16* __restrict__ Bh, const __nv_bfloat16* __restrict__ Bl,
    float* __restrict__ C, int Kd, int Nglob)
{
    extern __shared__ char smem[];
    const int tid = threadIdx.x;
    const int wid = tid >> 5;
    const int lane = tid & 31;
    const int warp_m = wid >> 2;          // 0..3 -> M offset 64*warp_m
    const int warp_n = wid & 3;           // 0..3 -> N offset 32*warp_n
    const int bx = blockIdx.x, by = blockIdx.y;

    const size_t a_row0 = (size_t)by * 256;
    const size_t b_row0 = (size_t)bx * 128;
    const int NKT = Kd / BK;

    // cp.async per-thread slots: r = tid>>3 (+64/iter), c8 = tid&7
    const int ld_r  = tid >> 3;          // 0..63
    const int ld_c8 = tid & 7;
    const uint32_t ld_sw = sw_off(ld_r, ld_c8);

    auto load_tile = [&](int s, int kt) {
        char* base = smem + s * STAGE_B;
        const size_t kcol = (size_t)kt * BK + ld_c8 * 8;
        // A hi/lo: 256 rows -> 4 iters of 64 rows each
#pragma unroll
        for (int v = 0; v < 2; v++) {
            const __nv_bfloat16* src = v ? Al : Ah;
            uint32_t dst0 = smem_u32(base + v * A_TILE_B) + ld_sw;
#pragma unroll
            for (int it = 0; it < 4; it++)
                CP_ASYNC16(dst0 + it * 64 * 128,
                           src + (a_row0 + ld_r + it * 64) * Kd + kcol);
        }
        // B hi/lo: 128 rows -> 2 iters of 64 rows each
#pragma unroll
        for (int v = 0; v < 2; v++) {
            const __nv_bfloat16* src = v ? Bl : Bh;
            uint32_t dst0 = smem_u32(base + 2 * A_TILE_B + v * B_TILE_B) + ld_sw;
#pragma unroll
            for (int it = 0; it < 2; it++)
                CP_ASYNC16(dst0 + it * 64 * 128,
                           src + (b_row0 + ld_r + it * 64) * Kd + kcol);
        }
    };

    load_tile(0, 0); CP_COMMIT();
    load_tile(1, 1); CP_COMMIT();

    float acc[4][4][4];
#pragma unroll
    for (int mt = 0; mt < 4; mt++)
#pragma unroll
        for (int nt = 0; nt < 4; nt++)
#pragma unroll
            for (int c = 0; c < 4; c++) acc[mt][nt][c] = 0.0f;

    const int lm_row = lane & 15;
    const int lm_hi  = lane >> 4;

#pragma unroll 1
    for (int kt = 0; kt < NKT; kt++) {
        CP_WAIT1();
        __syncthreads();
        char* buf = smem + (kt & 1) * STAGE_B;
        const uint32_t sAh = smem_u32(buf);
        const uint32_t sAl = sAh + A_TILE_B;
        const uint32_t sBh = sAh + 2 * A_TILE_B;
        const uint32_t sBl = sBh + B_TILE_B;

#pragma unroll
        for (int ks = 0; ks < 4; ks++) {
            const int chunk = ks * 2 + lm_hi;
            uint32_t a_h[4][4], a_l[4][4];
#pragma unroll
            for (int mt = 0; mt < 4; mt++) {
                const int row = warp_m * 64 + mt * 16 + lm_row;
                const uint32_t so = sw_off(row, chunk);
                LDSM_X4(a_h[mt][0], a_h[mt][1], a_h[mt][2], a_h[mt][3], sAh + so);
                LDSM_X4(a_l[mt][0], a_l[mt][1], a_l[mt][2], a_l[mt][3], sAl + so);
            }
            uint32_t b_h[4][2], b_l[4][2];
#pragma unroll
            for (int np = 0; np < 2; np++) {
                const int row = warp_n * 32 + np * 16 + lm_row;
                const uint32_t so = sw_off(row, chunk);
                uint32_t t0, t1, t2, t3;
                LDSM_X4(t0, t1, t2, t3, sBh + so);
                b_h[2 * np][0] = t0;     b_h[2 * np][1] = t2;
                b_h[2 * np + 1][0] = t1; b_h[2 * np + 1][1] = t3;
                LDSM_X4(t0, t1, t2, t3, sBl + so);
                b_l[2 * np][0] = t0;     b_l[2 * np][1] = t2;
                b_l[2 * np + 1][0] = t1; b_l[2 * np + 1][1] = t3;
            }
#pragma unroll
            for (int mt = 0; mt < 4; mt++)
#pragma unroll
                for (int nb = 0; nb < 4; nb++) {
                    float* d = acc[mt][nb];
                    MMA_BF16(d, a_h[mt], b_h[nb]);
                    MMA_BF16(d, a_h[mt], b_l[nb]);
                    MMA_BF16(d, a_l[mt], b_h[nb]);
                }
        }
        __syncthreads();
        if (kt + NSTAGE < NKT) load_tile(kt & 1, kt + NSTAGE);
        CP_COMMIT();
    }

    // Epilogue: registers -> C (float2 stores)
    const int g = lane >> 2;
    const int t2 = (lane & 3) * 2;
#pragma unroll
    for (int mt = 0; mt < 4; mt++) {
        const size_t r0 = a_row0 + warp_m * 64 + mt * 16 + g;
#pragma unroll
        for (int nt = 0; nt < 4; nt++) {
            const size_t col = b_row0 + warp_n * 32 + nt * 8 + t2;
            *reinterpret_cast<float2*>(&C[r0 * Nglob + col]) =
                make_float2(acc[mt][nt][0], acc[mt][nt][1]);
            *reinterpret_cast<float2*>(&C[(r0 + 8) * Nglob + col]) =
                make_float2(acc[mt][nt][2], acc[mt][nt][3]);
        }
    }
}

// ---------------------------------------------------------------------------
// f32 -> (hi, lo) bf16 split, elementwise
// ---------------------------------------------------------------------------
__device__ __forceinline__ void split1(float x, __nv_bfloat16& h, __nv_bfloat16& l) {
    h = __float2bfloat16(x);
    l = __float2bfloat16(x - __bfloat162float(h));
}

__global__ __launch_bounds__(256) void split_kernel(
    const float* __restrict__ in, __nv_bfloat16* __restrict__ hi,
    __nv_bfloat16* __restrict__ lo, int n4)
{
    int i = blockIdx.x * blockDim.x + threadIdx.x;
    if (i >= n4) return;
    float4 v = reinterpret_cast<const float4*>(in)[i];
    __nv_bfloat16 h0, h1, h2, h3, l0, l1, l2, l3;
    split1(v.x, h0, l0); split1(v.y, h1, l1);
    split1(v.z, h2, l2); split1(v.w, h3, l3);
    __nv_bfloat162* ph = reinterpret_cast<__nv_bfloat162*>(hi);
    __nv_bfloat162* pl = reinterpret_cast<__nv_bfloat162*>(lo);
    ph[2 * i + 0] = __halves2bfloat162(h0, h1);
    ph[2 * i + 1] = __halves2bfloat162(h2, h3);
    pl[2 * i + 0] = __halves2bfloat162(l0, l1);
    pl[2 * i + 1] = __halves2bfloat162(l2, l3);
}

// ---------------------------------------------------------------------------
// transpose + split: in f32 [R, C] -> out hi/lo bf16 [C, R]
// ---------------------------------------------------------------------------
__global__ __launch_bounds__(256) void transpose_split_kernel(
    const float* __restrict__ in, __nv_bfloat16* __restrict__ oh,
    __nv_bfloat16* __restrict__ ol, int R, int C)
{
    __shared__ float t[32][33];
    const int bx = blockIdx.x * 32;
    const int by = blockIdx.y * 32;
    const int tx = threadIdx.x, ty = threadIdx.y;   // 32 x 8
#pragma unroll
    for (int j = 0; j < 4; j++)
        t[ty + 8 * j][tx] = in[(size_t)(by + ty + 8 * j) * C + bx + tx];
    __syncthreads();
#pragma unroll
    for (int j = 0; j < 4; j++) {
        float v = t[tx][ty + 8 * j];
        __nv_bfloat16 h, l;
        split1(v, h, l);
        size_t o = (size_t)(bx + ty + 8 * j) * R + by + tx;
        oh[o] = h;
        ol[o] = l;
    }
}

// ---------------------------------------------------------------------------
// Fused scale + softmax over rows of S [SEQ, SEQ]; writes split bf16 P.
// ---------------------------------------------------------------------------
__global__ __launch_bounds__(256) void softmax_split_kernel(
    const float* __restrict__ S, __nv_bfloat16* __restrict__ Ph,
    __nv_bfloat16* __restrict__ Pl)
{
    const float scale = 0.03125f;   // 1/sqrt(1024)
    const float* row = S + (size_t)blockIdx.x * SEQ;
    const int t = threadIdx.x;

    __shared__ float smax[8];
    __shared__ float ssum[8];

    float4 v[4];
    float m = -1e30f;
#pragma unroll
    for (int i = 0; i < 4; i++) {
        v[i] = *reinterpret_cast<const float4*>(&row[t * 16 + i * 4]);
        v[i].x *= scale; v[i].y *= scale; v[i].z *= scale; v[i].w *= scale;
        m = fmaxf(m, fmaxf(fmaxf(v[i].x, v[i].y), fmaxf(v[i].z, v[i].w)));
    }
#pragma unroll
    for (int o = 16; o > 0; o >>= 1) m = fmaxf(m, __shfl_xor_sync(0xffffffffu, m, o));
    if ((t & 31) == 0) smax[t >> 5] = m;
    __syncthreads();
    m = smax[0];
#pragma unroll
    for (int w = 1; w < 8; w++) m = fmaxf(m, smax[w]);

    float s = 0.0f;
#pragma unroll
    for (int i = 0; i < 4; i++) {
        v[i].x = __expf(v[i].x - m); v[i].y = __expf(v[i].y - m);
        v[i].z = __expf(v[i].z - m); v[i].w = __expf(v[i].w - m);
        s += v[i].x + v[i].y + v[i].z + v[i].w;
    }
#pragma unroll
    for (int o = 16; o > 0; o >>= 1) s += __shfl_xor_sync(0xffffffffu, s, o);
    if ((t & 31) == 0) ssum[t >> 5] = s;
    __syncthreads();
    s = ssum[0];
#pragma unroll
    for (int w = 1; w < 8; w++) s += ssum[w];
    const float inv = 1.0f / s;

    __nv_bfloat162* ph = reinterpret_cast<__nv_bfloat162*>(
        Ph + (size_t)blockIdx.x * SEQ);
    __nv_bfloat162* pl = reinterpret_cast<__nv_bfloat162*>(
        Pl + (size_t)blockIdx.x * SEQ);
#pragma unroll
    for (int i = 0; i < 4; i++) {
        float f0 = v[i].x * inv, f1 = v[i].y * inv;
        float f2 = v[i].z * inv, f3 = v[i].w * inv;
        __nv_bfloat16 h0, h1, h2, h3, l0, l1, l2, l3;
        split1(f0, h0, l0); split1(f1, h1, l1);
        split1(f2, h2, l2); split1(f3, h3, l3);
        int idx = (t * 16 + i * 4) >> 1;
        ph[idx + 0] = __halves2bfloat162(h0, h1);
        ph[idx + 1] = __halves2bfloat162(h2, h3);
        pl[idx + 0] = __halves2bfloat162(l0, l1);
        pl[idx + 1] = __halves2bfloat162(l2, l3);
    }
}

// ---------------------------------------------------------------------------
extern "C" void kernel_launch(void* const* d_in, const int* in_sizes, int n_in,
                              void* d_out, int out_size)
{
    const float* x  = (const float*)d_in[0];
    const float* wq = (const float*)d_in[1];
    const float* wk = (const float*)d_in[2];
    const float* wv = (const float*)d_in[3];
    float* out = (float*)d_out;

    float *Q, *K, *V, *S;
    __nv_bfloat16 *Xh, *Xl, *Wqh, *Wql, *Wkh, *Wkl, *Wvh, *Wvl;
    __nv_bfloat16 *Qh, *Ql, *Kh, *Kl, *Vth, *Vtl, *Ph, *Pl;
    cudaGetSymbolAddress((void**)&Q, g_Q);
    cudaGetSymbolAddress((void**)&K, g_K);
    cudaGetSymbolAddress((void**)&V, g_V);
    cudaGetSymbolAddress((void**)&S, g_S);
    cudaGetSymbolAddress((void**)&Xh, g_Xh);   cudaGetSymbolAddress((void**)&Xl, g_Xl);
    cudaGetSymbolAddress((void**)&Wqh, g_Wqh); cudaGetSymbolAddress((void**)&Wql, g_Wql);
    cudaGetSymbolAddress((void**)&Wkh, g_Wkh); cudaGetSymbolAddress((void**)&Wkl, g_Wkl);
    cudaGetSymbolAddress((void**)&Wvh, g_Wvh); cudaGetSymbolAddress((void**)&Wvl, g_Wvl);
    cudaGetSymbolAddress((void**)&Qh, g_Qh);   cudaGetSymbolAddress((void**)&Ql, g_Ql);
    cudaGetSymbolAddress((void**)&Kh, g_Kh);   cudaGetSymbolAddress((void**)&Kl, g_Kl);
    cudaGetSymbolAddress((void**)&Vth, g_Vth); cudaGetSymbolAddress((void**)&Vtl, g_Vtl);
    cudaGetSymbolAddress((void**)&Ph, g_Ph);   cudaGetSymbolAddress((void**)&Pl, g_Pl);

    cudaFuncSetAttribute(hmma_gemm_nt,
                         cudaFuncAttributeMaxDynamicSharedMemorySize, GEMM_SMEM);

    const int nXd4 = SEQ * DMODEL / 4;

    // 1. Split X; transpose+split weights.
    split_kernel<<<(nXd4 + 255) / 256, 256>>>(x, Xh, Xl, nXd4);
    dim3 tb(32, 8);
    transpose_split_kernel<<<dim3(DMODEL / 32, DMODEL / 32), tb>>>(wq, Wqh, Wql, DMODEL, DMODEL);
    transpose_split_kernel<<<dim3(DMODEL / 32, DMODEL / 32), tb>>>(wk, Wkh, Wkl, DMODEL, DMODEL);
    transpose_split_kernel<<<dim3(DMODEL / 32, DMODEL / 32), tb>>>(wv, Wvh, Wvl, DMODEL, DMODEL);

    // 2. Projections: Q/K/V = X @ W  (B given as W^T [N,K])
    dim3 gp(DMODEL / 128, SEQ / 256);   // (8, 16)
    hmma_gemm_nt<<<gp, 512, GEMM_SMEM>>>(Xh, Xl, Wqh, Wql, Q, DMODEL, DMODEL);
    hmma_gemm_nt<<<gp, 512, GEMM_SMEM>>>(Xh, Xl, Wkh, Wkl, K, DMODEL, DMODEL);
    hmma_gemm_nt<<<gp, 512, GEMM_SMEM>>>(Xh, Xl, Wvh, Wvl, V, DMODEL, DMODEL);

    // 3. Split Q and K; transpose+split V.
    split_kernel<<<(nXd4 + 255) / 256, 256>>>(Q, Qh, Ql, nXd4);
    split_kernel<<<(nXd4 + 255) / 256, 256>>>(K, Kh, Kl, nXd4);
    transpose_split_kernel<<<dim3(DMODEL / 32, SEQ / 32), tb>>>(V, Vth, Vtl, SEQ, DMODEL);

    // 4. Scores: S = Q @ K^T
    dim3 gs(SEQ / 128, SEQ / 256);      // (32, 16)
    hmma_gemm_nt<<<gs, 512, GEMM_SMEM>>>(Qh, Ql, Kh, Kl, S, DMODEL, SEQ);

    // 5. Softmax(S/32) -> split P
    softmax_split_kernel<<<SEQ, 256>>>(S, Ph, Pl);

    // 6. Context: out = P @ V   (B = V^T [DMODEL, SEQ])
    dim3 gc(DMODEL / 128, SEQ / 256);   // (8, 16)
    hmma_gemm_nt<<<gc, 512, GEMM_SMEM>>>(Ph, Pl, Vth, Vtl, out, SEQ, DMODEL);
}

// round 7
// speedup vs baseline: 1.0644x; 1.0644x over previous
#include <cuda_runtime.h>
#include <cuda_fp16.h>
#include <cstdint>
#include <cstddef>

#define SEQ 4096
#define DMODEL 1024

// ---------------------------------------------------------------------------
// Scratch (allocation-free rule: device globals)
// ---------------------------------------------------------------------------
__device__ __align__(128) float g_Q[(size_t)SEQ * DMODEL];
__device__ __align__(128) float g_K[(size_t)SEQ * DMODEL];
__device__ __align__(128) float g_V[(size_t)SEQ * DMODEL];
__device__ __align__(128) float g_S[(size_t)SEQ * SEQ];

__device__ __align__(128) __half g_Xh[(size_t)SEQ * DMODEL];
__device__ __align__(128) __half g_Xl[(size_t)SEQ * DMODEL];
__device__ __align__(128) __half g_Wqh[(size_t)DMODEL * DMODEL];
__device__ __align__(128) __half g_Wql[(size_t)DMODEL * DMODEL];
__device__ __align__(128) __half g_Wkh[(size_t)DMODEL * DMODEL];
__device__ __align__(128) __half g_Wkl[(size_t)DMODEL * DMODEL];
__device__ __align__(128) __half g_Wvh[(size_t)DMODEL * DMODEL];
__device__ __align__(128) __half g_Wvl[(size_t)DMODEL * DMODEL];
__device__ __align__(128) __half g_Qh[(size_t)SEQ * DMODEL];
__device__ __align__(128) __half g_Ql[(size_t)SEQ * DMODEL];
__device__ __align__(128) __half g_Kh[(size_t)SEQ * DMODEL];
__device__ __align__(128) __half g_Kl[(size_t)SEQ * DMODEL];
__device__ __align__(128) __half g_Vth[(size_t)DMODEL * SEQ];
__device__ __align__(128) __half g_Vtl[(size_t)DMODEL * SEQ];
__device__ __align__(128) __half g_Ph[(size_t)SEQ * SEQ];
__device__ __align__(128) __half g_Pl[(size_t)SEQ * SEQ];

// ---------------------------------------------------------------------------
// PTX helpers (base PTX only)
// ---------------------------------------------------------------------------
__device__ __forceinline__ uint32_t smem_u32(const void* p) {
    uint32_t a;
    asm("{ .reg .u64 t; cvta.to.shared.u64 t, %1; cvt.u32.u64 %0, t; }"
        : "=r"(a) : "l"(p));
    return a;
}
#define CP_ASYNC16(dst, src) \
    asm volatile("cp.async.cg.shared.global [%0], [%1], 16;" \
                 :: "r"(dst), "l"(src) : "memory")
#define CP_COMMIT() asm volatile("cp.async.commit_group;" ::: "memory")
#define CP_WAIT2()  asm volatile("cp.async.wait_group 2;" ::: "memory")

#define LDSM_X4(r0, r1, r2, r3, addr) \
    asm volatile("ldmatrix.sync.aligned.m8n8.x4.shared.b16 {%0,%1,%2,%3}, [%4];" \
                 : "=r"(r0), "=r"(r1), "=r"(r2), "=r"(r3) : "r"(addr))

// fp16 inputs, fp32 accumulate (main hh pass)
#define MMA_F32ACC(d, a, b) \
    asm volatile("mma.sync.aligned.m16n8k16.row.col.f32.f16.f16.f32 " \
                 "{%0,%1,%2,%3}, {%4,%5,%6,%7}, {%8,%9}, {%0,%1,%2,%3};" \
                 : "+f"((d)[0]), "+f"((d)[1]), "+f"((d)[2]), "+f"((d)[3]) \
                 : "r"((a)[0]), "r"((a)[1]), "r"((a)[2]), "r"((a)[3]), \
                   "r"((b)[0]), "r"((b)[1]))

// fp16 inputs, fp16 accumulate (cross-term passes; small magnitudes)
#define MMA_F16ACC(d, a, b) \
    asm volatile("mma.sync.aligned.m16n8k16.row.col.f16.f16.f16.f16 " \
                 "{%0,%1}, {%2,%3,%4,%5}, {%6,%7}, {%0,%1};" \
                 : "+r"((d)[0]), "+r"((d)[1]) \
                 : "r"((a)[0]), "r"((a)[1]), "r"((a)[2]), "r"((a)[3]), \
                   "r"((b)[0]), "r"((b)[1]))

// ---------------------------------------------------------------------------
// HMMA GEMM:  C[M, Nglob] = (Ah+Al)[M, Kd] @ (Bh+Bl)[Nglob, Kd]^T
// fp16 split; pass hh -> fp32 acc; passes hl+lh -> shared fp16 acc.
// CTA tile 128x128x64, 256 threads, 8 warps (2x4), warp tile 64x32.
// 3-stage cp.async pipeline; SW128-XOR smem layout.
// ---------------------------------------------------------------------------
#define BK 64
#define TILE16 16384            // 128 x 64 fp16 = 16KB
#define STAGE_B (4 * TILE16)    // Ah|Al|Bh|Bl = 64KB
#define NSTAGE  3
#define GEMM_SMEM (NSTAGE * STAGE_B)   // 196608

__device__ __forceinline__ uint32_t sw_off(int row, int chunk) {
    uint32_t off = (uint32_t)(row * 128 + chunk * 16);
    return off ^ ((off >> 3) & 0x70);
}

__global__ __launch_bounds__(256, 1) void hmma_gemm_nt(
    const __half* __restrict__ Ah, const __half* __restrict__ Al,
    const __half* __restrict__ Bh, const __half* __restrict__ Bl,
    float* __restrict__ C, int Kd, int Nglob)
{
    extern __shared__ char smem[];
    const int tid = threadIdx.x;
    const int wid = tid >> 5;
    const int lane = tid & 31;
    const int warp_m = wid >> 2;          // 0..1 -> M offset 64*warp_m
    const int warp_n = wid & 3;           // 0..3 -> N offset 32*warp_n
    const int bx = blockIdx.x, by = blockIdx.y;

    const size_t a_row0 = (size_t)by * 128;
    const size_t b_row0 = (size_t)bx * 128;
    const int NKT = Kd / BK;

    // cp.async per-thread slots: r = tid>>3 (+32/iter), c8 = tid&7
    const int ld_r  = tid >> 3;          // 0..31
    const int ld_c8 = tid & 7;
    const uint32_t ld_sw = sw_off(ld_r, ld_c8);

    auto load_tile = [&](int s, int kt) {
        char* base = smem + s * STAGE_B;
        const size_t kcol = (size_t)kt * BK + ld_c8 * 8;
#pragma unroll
        for (int v = 0; v < 4; v++) {
            const __half* src =
                (v == 0) ? Ah : (v == 1) ? Al : (v == 2) ? Bh : Bl;
            const size_t row0 = (v < 2) ? a_row0 : b_row0;
            uint32_t dst0 = smem_u32(base + v * TILE16) + ld_sw;
#pragma unroll
            for (int it = 0; it < 4; it++)
                CP_ASYNC16(dst0 + it * 32 * 128,
                           src + (row0 + ld_r + it * 32) * Kd + kcol);
        }
    };

    load_tile(0, 0); CP_COMMIT();
    load_tile(1, 1); CP_COMMIT();
    load_tile(2, 2); CP_COMMIT();

    float acc32[4][4][4];
    uint32_t acc16[4][4][2];
#pragma unroll
    for (int mt = 0; mt < 4; mt++)
#pragma unroll
        for (int nt = 0; nt < 4; nt++) {
#pragma unroll
            for (int c = 0; c < 4; c++) acc32[mt][nt][c] = 0.0f;
            acc16[mt][nt][0] = 0u;
            acc16[mt][nt][1] = 0u;
        }

    const int lm_row = lane & 15;
    const int lm_hi  = lane >> 4;

#pragma unroll 1
    for (int kt = 0; kt < NKT; kt++) {
        CP_WAIT2();
        __syncthreads();
        char* buf = smem + (kt % NSTAGE) * STAGE_B;
        const uint32_t sAh = smem_u32(buf);
        const uint32_t sAl = sAh + TILE16;
        const uint32_t sBh = sAh + 2 * TILE16;
        const uint32_t sBl = sAh + 3 * TILE16;

#pragma unroll
        for (int ks = 0; ks < 4; ks++) {
            const int chunk = ks * 2 + lm_hi;
            uint32_t a_h[4][4], a_l[4][4];
#pragma unroll
            for (int mt = 0; mt < 4; mt++) {
                const int row = warp_m * 64 + mt * 16 + lm_row;
                const uint32_t so = sw_off(row, chunk);
                LDSM_X4(a_h[mt][0], a_h[mt][1], a_h[mt][2], a_h[mt][3], sAh + so);
                LDSM_X4(a_l[mt][0], a_l[mt][1], a_l[mt][2], a_l[mt][3], sAl + so);
            }
            uint32_t b_h[4][2], b_l[4][2];
#pragma unroll
            for (int np = 0; np < 2; np++) {
                const int row = warp_n * 32 + np * 16 + lm_row;
                const uint32_t so = sw_off(row, chunk);
                uint32_t t0, t1, t2, t3;
                LDSM_X4(t0, t1, t2, t3, sBh + so);
                b_h[2 * np][0] = t0;     b_h[2 * np][1] = t2;
                b_h[2 * np + 1][0] = t1; b_h[2 * np + 1][1] = t3;
                LDSM_X4(t0, t1, t2, t3, sBl + so);
                b_l[2 * np][0] = t0;     b_l[2 * np][1] = t2;
                b_l[2 * np + 1][0] = t1; b_l[2 * np + 1][1] = t3;
            }
#pragma unroll
            for (int mt = 0; mt < 4; mt++)
#pragma unroll
                for (int nb = 0; nb < 4; nb++) {
                    MMA_F32ACC(acc32[mt][nb], a_h[mt], b_h[nb]);
                    MMA_F16ACC(acc16[mt][nb], a_h[mt], b_l[nb]);
                    MMA_F16ACC(acc16[mt][nb], a_l[mt], b_h[nb]);
                }
        }
        __syncthreads();
        if (kt + NSTAGE < NKT) load_tile(kt % NSTAGE, kt + NSTAGE);
        CP_COMMIT();
    }

    // Epilogue: acc32 + float(acc16) -> C (float2 stores)
    const int g = lane >> 2;
    const int t2 = (lane & 3) * 2;
#pragma unroll
    for (int mt = 0; mt < 4; mt++) {
        const size_t r0 = a_row0 + warp_m * 64 + mt * 16 + g;
#pragma unroll
        for (int nt = 0; nt < 4; nt++) {
            float2 x0 = __half22float2(
                *reinterpret_cast<__half2*>(&acc16[mt][nt][0]));
            float2 x1 = __half22float2(
                *reinterpret_cast<__half2*>(&acc16[mt][nt][1]));
            const size_t col = b_row0 + warp_n * 32 + nt * 8 + t2;
            *reinterpret_cast<float2*>(&C[r0 * Nglob + col]) =
                make_float2(acc32[mt][nt][0] + x0.x, acc32[mt][nt][1] + x0.y);
            *reinterpret_cast<float2*>(&C[(r0 + 8) * Nglob + col]) =
                make_float2(acc32[mt][nt][2] + x1.x, acc32[mt][nt][3] + x1.y);
        }
    }
}

// ---------------------------------------------------------------------------
// f32 -> (hi, lo) fp16 split, elementwise
// ---------------------------------------------------------------------------
__device__ __forceinline__ void split1(float x, __half& h, __half& l) {
    h = __float2half_rn(x);
    l = __float2half_rn(x - __half2float(h));
}

__global__ __launch_bounds__(256) void split_kernel(
    const float* __restrict__ in, __half* __restrict__ hi,
    __half* __restrict__ lo, int n4)
{
    int i = blockIdx.x * blockDim.x + threadIdx.x;
    if (i >= n4) return;
    float4 v = reinterpret_cast<const float4*>(in)[i];
    __half h0, h1, h2, h3, l0, l1, l2, l3;
    split1(v.x, h0, l0); split1(v.y, h1, l1);
    split1(v.z, h2, l2); split1(v.w, h3, l3);
    __half2* ph = reinterpret_cast<__half2*>(hi);
    __half2* pl = reinterpret_cast<__half2*>(lo);
    ph[2 * i + 0] = __halves2half2(h0, h1);
    ph[2 * i + 1] = __halves2half2(h2, h3);
    pl[2 * i + 0] = __halves2half2(l0, l1);
    pl[2 * i + 1] = __halves2half2(l2, l3);
}

// ---------------------------------------------------------------------------
// transpose + split: in f32 [R, C] -> out hi/lo fp16 [C, R]
// ---------------------------------------------------------------------------
__global__ __launch_bounds__(256) void transpose_split_kernel(
    const float* __restrict__ in, __half* __restrict__ oh,
    __half* __restrict__ ol, int R, int C)
{
    __shared__ float t[32][33];
    const int bx = blockIdx.x * 32;
    const int by = blockIdx.y * 32;
    const int tx = threadIdx.x, ty = threadIdx.y;   // 32 x 8
#pragma unroll
    for (int j = 0; j < 4; j++)
        t[ty + 8 * j][tx] = in[(size_t)(by + ty + 8 * j) * C + bx + tx];
    __syncthreads();
#pragma unroll
    for (int j = 0; j < 4; j++) {
        float v = t[tx][ty + 8 * j];
        __half h, l;
        split1(v, h, l);
        size_t o = (size_t)(bx + ty + 8 * j) * R + by + tx;
        oh[o] = h;
        ol[o] = l;
    }
}

// ---------------------------------------------------------------------------
// Fused scale + softmax over rows of S [SEQ, SEQ]; writes split fp16 P.
// ---------------------------------------------------------------------------
__global__ __launch_bounds__(256) void softmax_split_kernel(
    const float* __restrict__ S, __half* __restrict__ Ph,
    __half* __restrict__ Pl)
{
    const float scale = 0.03125f;   // 1/sqrt(1024)
    const float* row = S + (size_t)blockIdx.x * SEQ;
    const int t = threadIdx.x;

    __shared__ float smax[8];
    __shared__ float ssum[8];

    float4 v[4];
    float m = -1e30f;
#pragma unroll
    for (int i = 0; i < 4; i++) {
        v[i] = *reinterpret_cast<const float4*>(&row[t * 16 + i * 4]);
        v[i].x *= scale; v[i].y *= scale; v[i].z *= scale; v[i].w *= scale;
        m = fmaxf(m, fmaxf(fmaxf(v[i].x, v[i].y), fmaxf(v[i].z, v[i].w)));
    }
#pragma unroll
    for (int o = 16; o > 0; o >>= 1) m = fmaxf(m, __shfl_xor_sync(0xffffffffu, m, o));
    if ((t & 31) == 0) smax[t >> 5] = m;
    __syncthreads();
    m = smax[0];
#pragma unroll
    for (int w = 1; w < 8; w++) m = fmaxf(m, smax[w]);

    float s = 0.0f;
#pragma unroll
    for (int i = 0; i < 4; i++) {
        v[i].x = __expf(v[i].x - m); v[i].y = __expf(v[i].y - m);
        v[i].z = __expf(v[i].z - m); v[i].w = __expf(v[i].w - m);
        s += v[i].x + v[i].y + v[i].z + v[i].w;
    }
#pragma unroll
    for (int o = 16; o > 0; o >>= 1) s += __shfl_xor_sync(0xffffffffu, s, o);
    if ((t & 31) == 0) ssum[t >> 5] = s;
    __syncthreads();
    s = ssum[0];
#pragma unroll
    for (int w = 1; w < 8; w++) s += ssum[w];
    const float inv = 1.0f / s;

    __half2* ph = reinterpret_cast<__half2*>(Ph + (size_t)blockIdx.x * SEQ);
    __half2* pl = reinterpret_cast<__half2*>(Pl + (size_t)blockIdx.x * SEQ);
#pragma unroll
    for (int i = 0; i < 4; i++) {
        float f0 = v[i].x * inv, f1 = v[i].y * inv;
        float f2 = v[i].z * inv, f3 = v[i].w * inv;
        __half h0, h1, h2, h3, l0, l1, l2, l3;
        split1(f0, h0, l0); split1(f1, h1, l1);
        split1(f2, h2, l2); split1(f3, h3, l3);
        int idx = (t * 16 + i * 4) >> 1;
        ph[idx + 0] = __halves2half2(h0, h1);
        ph[idx + 1] = __halves2half2(h2, h3);
        pl[idx + 0] = __halves2half2(l0, l1);
        pl[idx + 1] = __halves2half2(l2, l3);
    }
}

// ---------------------------------------------------------------------------
extern "C" void kernel_launch(void* const* d_in, const int* in_sizes, int n_in,
                              void* d_out, int out_size)
{
    const float* x  = (const float*)d_in[0];
    const float* wq = (const float*)d_in[1];
    const float* wk = (const float*)d_in[2];
    const float* wv = (const float*)d_in[3];
    float* out = (float*)d_out;

    float *Q, *K, *V, *S;
    __half *Xh, *Xl, *Wqh, *Wql, *Wkh, *Wkl, *Wvh, *Wvl;
    __half *Qh, *Ql, *Kh, *Kl, *Vth, *Vtl, *Ph, *Pl;
    cudaGetSymbolAddress((void**)&Q, g_Q);
    cudaGetSymbolAddress((void**)&K, g_K);
    cudaGetSymbolAddress((void**)&V, g_V);
    cudaGetSymbolAddress((void**)&S, g_S);
    cudaGetSymbolAddress((void**)&Xh, g_Xh);   cudaGetSymbolAddress((void**)&Xl, g_Xl);
    cudaGetSymbolAddress((void**)&Wqh, g_Wqh); cudaGetSymbolAddress((void**)&Wql, g_Wql);
    cudaGetSymbolAddress((void**)&Wkh, g_Wkh); cudaGetSymbolAddress((void**)&Wkl, g_Wkl);
    cudaGetSymbolAddress((void**)&Wvh, g_Wvh); cudaGetSymbolAddress((void**)&Wvl, g_Wvl);
    cudaGetSymbolAddress((void**)&Qh, g_Qh);   cudaGetSymbolAddress((void**)&Ql, g_Ql);
    cudaGetSymbolAddress((void**)&Kh, g_Kh);   cudaGetSymbolAddress((void**)&Kl, g_Kl);
    cudaGetSymbolAddress((void**)&Vth, g_Vth); cudaGetSymbolAddress((void**)&Vtl, g_Vtl);
    cudaGetSymbolAddress((void**)&Ph, g_Ph);   cudaGetSymbolAddress((void**)&Pl, g_Pl);

    cudaFuncSetAttribute(hmma_gemm_nt,
                         cudaFuncAttributeMaxDynamicSharedMemorySize, GEMM_SMEM);

    const int nXd4 = SEQ * DMODEL / 4;

    // 1. Split X; transpose+split weights.
    split_kernel<<<(nXd4 + 255) / 256, 256>>>(x, Xh, Xl, nXd4);
    dim3 tb(32, 8);
    transpose_split_kernel<<<dim3(DMODEL / 32, DMODEL / 32), tb>>>(wq, Wqh, Wql, DMODEL, DMODEL);
    transpose_split_kernel<<<dim3(DMODEL / 32, DMODEL / 32), tb>>>(wk, Wkh, Wkl, DMODEL, DMODEL);
    transpose_split_kernel<<<dim3(DMODEL / 32, DMODEL / 32), tb>>>(wv, Wvh, Wvl, DMODEL, DMODEL);

    // 2. Projections: Q/K/V = X @ W  (B given as W^T [N,K])
    dim3 gp(DMODEL / 128, SEQ / 128);   // (8, 32)
    hmma_gemm_nt<<<gp, 256, GEMM_SMEM>>>(Xh, Xl, Wqh, Wql, Q, DMODEL, DMODEL);
    hmma_gemm_nt<<<gp, 256, GEMM_SMEM>>>(Xh, Xl, Wkh, Wkl, K, DMODEL, DMODEL);
    hmma_gemm_nt<<<gp, 256, GEMM_SMEM>>>(Xh, Xl, Wvh, Wvl, V, DMODEL, DMODEL);

    // 3. Split Q and K; transpose+split V.
    split_kernel<<<(nXd4 + 255) / 256, 256>>>(Q, Qh, Ql, nXd4);
    split_kernel<<<(nXd4 + 255) / 256, 256>>>(K, Kh, Kl, nXd4);
    transpose_split_kernel<<<dim3(DMODEL / 32, SEQ / 32), tb>>>(V, Vth, Vtl, SEQ, DMODEL);

    // 4. Scores: S = Q @ K^T
    dim3 gs(SEQ / 128, SEQ / 128);      // (32, 32)
    hmma_gemm_nt<<<gs, 256, GEMM_SMEM>>>(Qh, Ql, Kh, Kl, S, DMODEL, SEQ);

    // 5. Softmax(S/32) -> split P
    softmax_split_kernel<<<SEQ, 256>>>(S, Ph, Pl);

    // 6. Context: out = P @ V   (B = V^T [DMODEL, SEQ])
    dim3 gc(DMODEL / 128, SEQ / 128);   // (8, 32)
    hmma_gemm_nt<<<gc, 256, GEMM_SMEM>>>(Ph, Pl, Vth, Vtl, out, SEQ, DMODEL);
}

// round 11
// speedup vs baseline: 1.6681x; 1.5672x over previous
#include <cuda_runtime.h>
#include <cuda_fp16.h>
#include <cstdint>
#include <cstddef>

#define SEQ 4096
#define DMODEL 1024

// ---------------------------------------------------------------------------
// Scratch (allocation-free rule: device globals)
// ---------------------------------------------------------------------------
__device__ __align__(128) float g_Q[(size_t)SEQ * DMODEL];
__device__ __align__(128) float g_K[(size_t)SEQ * DMODEL];
__device__ __align__(128) float g_V[(size_t)SEQ * DMODEL];
__device__ __align__(128) float g_S[(size_t)SEQ * SEQ];   // scores -> softmax in place

__device__ __align__(128) __half g_Xh[(size_t)SEQ * DMODEL];
__device__ __align__(128) __half g_Xl[(size_t)SEQ * DMODEL];
__device__ __align__(128) __half g_Wqh[(size_t)DMODEL * DMODEL];
__device__ __align__(128) __half g_Wql[(size_t)DMODEL * DMODEL];
__device__ __align__(128) __half g_Wkh[(size_t)DMODEL * DMODEL];
__device__ __align__(128) __half g_Wkl[(size_t)DMODEL * DMODEL];
__device__ __align__(128) __half g_Wvh[(size_t)DMODEL * DMODEL];
__device__ __align__(128) __half g_Wvl[(size_t)DMODEL * DMODEL];
__device__ __align__(128) __half g_Qh[(size_t)SEQ * DMODEL];
__device__ __align__(128) __half g_Ql[(size_t)SEQ * DMODEL];
__device__ __align__(128) __half g_Kh[(size_t)SEQ * DMODEL];
__device__ __align__(128) __half g_Kl[(size_t)SEQ * DMODEL];

// ---------------------------------------------------------------------------
// PTX helpers (base PTX only)
// ---------------------------------------------------------------------------
__device__ __forceinline__ uint32_t smem_u32(const void* p) {
    uint32_t a;
    asm("{ .reg .u64 t; cvta.to.shared.u64 t, %1; cvt.u32.u64 %0, t; }"
        : "=r"(a) : "l"(p));
    return a;
}
#define CP_ASYNC16(dst, src) \
    asm volatile("cp.async.cg.shared.global [%0], [%1], 16;" \
                 :: "r"(dst), "l"(src) : "memory")
#define CP_COMMIT() asm volatile("cp.async.commit_group;" ::: "memory")
#define CP_WAIT2()  asm volatile("cp.async.wait_group 2;" ::: "memory")

#define LDSM_X4(r0, r1, r2, r3, addr) \
    asm volatile("ldmatrix.sync.aligned.m8n8.x4.shared.b16 {%0,%1,%2,%3}, [%4];" \
                 : "=r"(r0), "=r"(r1), "=r"(r2), "=r"(r3) : "r"(addr))

#define MMA_F32ACC(d, a, b) \
    asm volatile("mma.sync.aligned.m16n8k16.row.col.f32.f16.f16.f32 " \
                 "{%0,%1,%2,%3}, {%4,%5,%6,%7}, {%8,%9}, {%0,%1,%2,%3};" \
                 : "+f"((d)[0]), "+f"((d)[1]), "+f"((d)[2]), "+f"((d)[3]) \
                 : "r"((a)[0]), "r"((a)[1]), "r"((a)[2]), "r"((a)[3]), \
                   "r"((b)[0]), "r"((b)[1]))

#define MMA_F16ACC(d, a, b) \
    asm volatile("mma.sync.aligned.m16n8k16.row.col.f16.f16.f16.f16 " \
                 "{%0,%1}, {%2,%3,%4,%5}, {%6,%7}, {%0,%1};" \
                 : "+r"((d)[0]), "+r"((d)[1]) \
                 : "r"((a)[0]), "r"((a)[1]), "r"((a)[2]), "r"((a)[3]), \
                   "r"((b)[0]), "r"((b)[1]))

__device__ __forceinline__ uint32_t sw_off(int row, int chunk) {
    uint32_t off = (uint32_t)(row * 128 + chunk * 16);
    return off ^ ((off >> 3) & 0x70);
}

// ---------------------------------------------------------------------------
// HMMA GEMM (fp16 split, validated): hh -> fp32 acc; hl + lh -> fp16 acc.
// CTA 128x128x64, 256 thr, 8 warps (2x4), warp tile 64x32, 3-stage cp.async.
// ---------------------------------------------------------------------------
#define TILE_128B 16384              // 128 rows x 128 bytes
#define STAGE_B (4 * TILE_128B)      // Ah|Al|Bh|Bl = 64KB
#define NSTAGE  3
#define GEMM_SMEM (NSTAGE * STAGE_B) // 196608

__global__ __launch_bounds__(256, 1) void hmma_gemm_nt(
    const __half* __restrict__ Ah, const __half* __restrict__ Al,
    const __half* __restrict__ Bh, const __half* __restrict__ Bl,
    float* __restrict__ C, int Kd, int Nglob)
{
    extern __shared__ char smem[];
    const int tid = threadIdx.x;
    const int wid = tid >> 5;
    const int lane = tid & 31;
    const int warp_m = wid >> 2;
    const int warp_n = wid & 3;
    const int bx = blockIdx.x, by = blockIdx.y;

    const size_t a_row0 = (size_t)by * 128;
    const size_t b_row0 = (size_t)bx * 128;
    const int NKT = Kd / 64;

    const int ld_r  = tid >> 3;
    const int ld_c8 = tid & 7;
    const uint32_t ld_sw = sw_off(ld_r, ld_c8);

    auto load_tile = [&](int s, int kt) {
        char* base = smem + s * STAGE_B;
        const size_t kcol = (size_t)kt * 64 + ld_c8 * 8;
#pragma unroll
        for (int v = 0; v < 4; v++) {
            const __half* src =
                (v == 0) ? Ah : (v == 1) ? Al : (v == 2) ? Bh : Bl;
            const size_t row0 = (v < 2) ? a_row0 : b_row0;
            uint32_t dst0 = smem_u32(base + v * TILE_128B) + ld_sw;
#pragma unroll
            for (int it = 0; it < 4; it++)
                CP_ASYNC16(dst0 + it * 32 * 128,
                           src + (row0 + ld_r + it * 32) * Kd + kcol);
        }
    };

    load_tile(0, 0); CP_COMMIT();
    load_tile(1, 1); CP_COMMIT();
    load_tile(2, 2); CP_COMMIT();

    float acc32[4][4][4];
    uint32_t acc16[4][4][2];
#pragma unroll
    for (int mt = 0; mt < 4; mt++)
#pragma unroll
        for (int nt = 0; nt < 4; nt++) {
#pragma unroll
            for (int c = 0; c < 4; c++) acc32[mt][nt][c] = 0.0f;
            acc16[mt][nt][0] = 0u;
            acc16[mt][nt][1] = 0u;
        }

    const int lm_row = lane & 15;
    const int lm_hi  = lane >> 4;

#pragma unroll 1
    for (int kt = 0; kt < NKT; kt++) {
        CP_WAIT2();
        __syncthreads();
        char* buf = smem + (kt % NSTAGE) * STAGE_B;
        const uint32_t sAh = smem_u32(buf);
        const uint32_t sAl = sAh + TILE_128B;
        const uint32_t sBh = sAh + 2 * TILE_128B;
        const uint32_t sBl = sAh + 3 * TILE_128B;

#pragma unroll
        for (int ks = 0; ks < 4; ks++) {
            const int chunk = ks * 2 + lm_hi;
            uint32_t a_h[4][4], a_l[4][4];
#pragma unroll
            for (int mt = 0; mt < 4; mt++) {
                const int row = warp_m * 64 + mt * 16 + lm_row;
                const uint32_t so = sw_off(row, chunk);
                LDSM_X4(a_h[mt][0], a_h[mt][1], a_h[mt][2], a_h[mt][3], sAh + so);
                LDSM_X4(a_l[mt][0], a_l[mt][1], a_l[mt][2], a_l[mt][3], sAl + so);
            }
            uint32_t b_h[4][2], b_l[4][2];
#pragma unroll
            for (int np = 0; np < 2; np++) {
                const int row = warp_n * 32 + np * 16 + lm_row;
                const uint32_t so = sw_off(row, chunk);
                uint32_t t0, t1, t2, t3;
                LDSM_X4(t0, t1, t2, t3, sBh + so);
                b_h[2 * np][0] = t0;     b_h[2 * np][1] = t2;
                b_h[2 * np + 1][0] = t1; b_h[2 * np + 1][1] = t3;
                LDSM_X4(t0, t1, t2, t3, sBl + so);
                b_l[2 * np][0] = t0;     b_l[2 * np][1] = t2;
                b_l[2 * np + 1][0] = t1; b_l[2 * np + 1][1] = t3;
            }
#pragma unroll
            for (int mt = 0; mt < 4; mt++)
#pragma unroll
                for (int nb = 0; nb < 4; nb++) {
                    MMA_F32ACC(acc32[mt][nb], a_h[mt], b_h[nb]);
                    MMA_F16ACC(acc16[mt][nb], a_h[mt], b_l[nb]);
                    MMA_F16ACC(acc16[mt][nb], a_l[mt], b_h[nb]);
                }
        }
        __syncthreads();
        if (kt + NSTAGE < NKT) load_tile(kt % NSTAGE, kt + NSTAGE);
        CP_COMMIT();
    }

    const int g = lane >> 2;
    const int t2 = (lane & 3) * 2;
#pragma unroll
    for (int mt = 0; mt < 4; mt++) {
        const size_t r0 = a_row0 + warp_m * 64 + mt * 16 + g;
#pragma unroll
        for (int nt = 0; nt < 4; nt++) {
            float2 x0 = __half22float2(
                *reinterpret_cast<__half2*>(&acc16[mt][nt][0]));
            float2 x1 = __half22float2(
                *reinterpret_cast<__half2*>(&acc16[mt][nt][1]));
            const size_t col = b_row0 + warp_n * 32 + nt * 8 + t2;
            *reinterpret_cast<float2*>(&C[r0 * Nglob + col]) =
                make_float2(acc32[mt][nt][0] + x0.x, acc32[mt][nt][1] + x0.y);
            *reinterpret_cast<float2*>(&C[(r0 + 8) * Nglob + col]) =
                make_float2(acc32[mt][nt][2] + x1.x, acc32[mt][nt][3] + x1.y);
        }
    }
}

// ---------------------------------------------------------------------------
// f32 -> (hi, lo) fp16 split helpers
// ---------------------------------------------------------------------------
__device__ __forceinline__ void split1(float x, __half& h, __half& l) {
    h = __float2half_rn(x);
    l = __float2half_rn(x - __half2float(h));
}

__global__ __launch_bounds__(256) void split_kernel(
    const float* __restrict__ in, __half* __restrict__ hi,
    __half* __restrict__ lo, int n4)
{
    int i = blockIdx.x * blockDim.x + threadIdx.x;
    if (i >= n4) return;
    float4 v = reinterpret_cast<const float4*>(in)[i];
    __half h0, h1, h2, h3, l0, l1, l2, l3;
    split1(v.x, h0, l0); split1(v.y, h1, l1);
    split1(v.z, h2, l2); split1(v.w, h3, l3);
    __half2* ph = reinterpret_cast<__half2*>(hi);
    __half2* pl = reinterpret_cast<__half2*>(lo);
    ph[2 * i + 0] = __halves2half2(h0, h1);
    ph[2 * i + 1] = __halves2half2(h2, h3);
    pl[2 * i + 0] = __halves2half2(l0, l1);
    pl[2 * i + 1] = __halves2half2(l2, l3);
}

// transpose + split: in f32 [R, C] -> out hi/lo fp16 [C, R]
__global__ __launch_bounds__(256) void transpose_split_kernel(
    const float* __restrict__ in, __half* __restrict__ oh,
    __half* __restrict__ ol, int R, int C)
{
    __shared__ float tb[32][33];
    const int bx = blockIdx.x * 32;
    const int by = blockIdx.y * 32;
    const int tx = threadIdx.x, ty = threadIdx.y;
#pragma unroll
    for (int j = 0; j < 4; j++)
        tb[ty + 8 * j][tx] = in[(size_t)(by + ty + 8 * j) * C + bx + tx];
    __syncthreads();
#pragma unroll
    for (int j = 0; j < 4; j++) {
        float v = tb[tx][ty + 8 * j];
        __half h, l;
        split1(v, h, l);
        size_t o = (size_t)(bx + ty + 8 * j) * R + by + tx;
        oh[o] = h;
        ol[o] = l;
    }
}

// ---------------------------------------------------------------------------
// Fused scale + softmax over rows of S [SEQ, SEQ], fp32 p written IN PLACE.
// ---------------------------------------------------------------------------
__global__ __launch_bounds__(256) void softmax_inplace_kernel(float* __restrict__ S)
{
    const float scale = 0.03125f;   // 1/sqrt(1024)
    float* row = S + (size_t)blockIdx.x * SEQ;
    const int t = threadIdx.x;

    __shared__ float smax[8];
    __shared__ float ssum[8];

    float4 v[4];
    float m = -1e30f;
#pragma unroll
    for (int i = 0; i < 4; i++) {
        v[i] = *reinterpret_cast<const float4*>(&row[t * 16 + i * 4]);
        v[i].x *= scale; v[i].y *= scale; v[i].z *= scale; v[i].w *= scale;
        m = fmaxf(m, fmaxf(fmaxf(v[i].x, v[i].y), fmaxf(v[i].z, v[i].w)));
    }
#pragma unroll
    for (int o = 16; o > 0; o >>= 1) m = fmaxf(m, __shfl_xor_sync(0xffffffffu, m, o));
    if ((t & 31) == 0) smax[t >> 5] = m;
    __syncthreads();
    m = smax[0];
#pragma unroll
    for (int w = 1; w < 8; w++) m = fmaxf(m, smax[w]);

    float s = 0.0f;
#pragma unroll
    for (int i = 0; i < 4; i++) {
        v[i].x = __expf(v[i].x - m); v[i].y = __expf(v[i].y - m);
        v[i].z = __expf(v[i].z - m); v[i].w = __expf(v[i].w - m);
        s += v[i].x + v[i].y + v[i].z + v[i].w;
    }
#pragma unroll
    for (int o = 16; o > 0; o >>= 1) s += __shfl_xor_sync(0xffffffffu, s, o);
    if ((t & 31) == 0) ssum[t >> 5] = s;
    __syncthreads();
    s = ssum[0];
#pragma unroll
    for (int w = 1; w < 8; w++) s += ssum[w];
    const float inv = 1.0f / s;

#pragma unroll
    for (int i = 0; i < 4; i++) {
        v[i].x *= inv; v[i].y *= inv; v[i].z *= inv; v[i].w *= inv;
        *reinterpret_cast<float4*>(&row[t * 16 + i * 4]) = v[i];
    }
}

// ---------------------------------------------------------------------------
// Sparse PV: out[s,:] = sum_t P[s,t] * V[t,:], restricted to P > 1e-10.
// One block per row; deterministic block-scan compaction (no atomics).
// Dropped mass <= 4096e-10 -> abs err ~1e-8 * |V|: negligible.
// ---------------------------------------------------------------------------
__global__ __launch_bounds__(256) void pv_gather_kernel(
    const float* __restrict__ P, const float* __restrict__ V,
    float* __restrict__ out)
{
    __shared__ int   s_idx[SEQ];
    __shared__ float s_p[SEQ];
    __shared__ int   warp_base[9];

    const int srow = blockIdx.x;
    const int t = threadIdx.x;
    const float* prow = P + (size_t)srow * SEQ;
    const float THR = 1e-10f;

    // pass 1: count my strided candidates (cols t, t+256, ...)
    int cnt = 0;
#pragma unroll
    for (int i = 0; i < 16; i++)
        if (prow[t + i * 256] > THR) cnt++;

    // block exclusive scan (deterministic order by tid)
    int pre = cnt;
#pragma unroll
    for (int o = 1; o < 32; o <<= 1) {
        int v = __shfl_up_sync(0xffffffffu, pre, o);
        if ((t & 31) >= o) pre += v;
    }
    if ((t & 31) == 31) warp_base[(t >> 5) + 1] = pre;
    __syncthreads();
    if (t == 0) {
        warp_base[0] = 0;
        for (int w = 1; w <= 8; w++) warp_base[w] += warp_base[w - 1];
    }
    __syncthreads();
    int k = warp_base[t >> 5] + pre - cnt;

    // pass 2: compact (re-reads are L1 hits)
#pragma unroll
    for (int i = 0; i < 16; i++) {
        int col = t + i * 256;
        float p = prow[col];
        if (p > THR) { s_idx[k] = col; s_p[k] = p; k++; }
    }
    __syncthreads();

    const int n = warp_base[8];
    float a0 = 0.0f, a1 = 0.0f, a2 = 0.0f, a3 = 0.0f;
    for (int i = 0; i < n; i++) {
        const float p = s_p[i];
        float4 v = *reinterpret_cast<const float4*>(
            &V[(size_t)s_idx[i] * DMODEL + t * 4]);
        a0 = fmaf(p, v.x, a0); a1 = fmaf(p, v.y, a1);
        a2 = fmaf(p, v.z, a2); a3 = fmaf(p, v.w, a3);
    }
    *reinterpret_cast<float4*>(&out[(size_t)srow * DMODEL + t * 4]) =
        make_float4(a0, a1, a2, a3);
}

// ---------------------------------------------------------------------------
extern "C" void kernel_launch(void* const* d_in, const int* in_sizes, int n_in,
                              void* d_out, int out_size)
{
    const float* x  = (const float*)d_in[0];
    const float* wq = (const float*)d_in[1];
    const float* wk = (const float*)d_in[2];
    const float* wv = (const float*)d_in[3];
    float* out = (float*)d_out;

    float *Q, *K, *V, *S;
    __half *Xh, *Xl, *Wqh, *Wql, *Wkh, *Wkl, *Wvh, *Wvl, *Qh, *Ql, *Kh, *Kl;
    cudaGetSymbolAddress((void**)&Q, g_Q);
    cudaGetSymbolAddress((void**)&K, g_K);
    cudaGetSymbolAddress((void**)&V, g_V);
    cudaGetSymbolAddress((void**)&S, g_S);
    cudaGetSymbolAddress((void**)&Xh, g_Xh);   cudaGetSymbolAddress((void**)&Xl, g_Xl);
    cudaGetSymbolAddress((void**)&Wqh, g_Wqh); cudaGetSymbolAddress((void**)&Wql, g_Wql);
    cudaGetSymbolAddress((void**)&Wkh, g_Wkh); cudaGetSymbolAddress((void**)&Wkl, g_Wkl);
    cudaGetSymbolAddress((void**)&Wvh, g_Wvh); cudaGetSymbolAddress((void**)&Wvl, g_Wvl);
    cudaGetSymbolAddress((void**)&Qh, g_Qh);   cudaGetSymbolAddress((void**)&Ql, g_Ql);
    cudaGetSymbolAddress((void**)&Kh, g_Kh);   cudaGetSymbolAddress((void**)&Kl, g_Kl);

    cudaFuncSetAttribute(hmma_gemm_nt,
                         cudaFuncAttributeMaxDynamicSharedMemorySize, GEMM_SMEM);

    const int nXd4 = SEQ * DMODEL / 4;
    dim3 tb(32, 8);

    // 1. Split X; transpose+split weights.
    split_kernel<<<(nXd4 + 255) / 256, 256>>>(x, Xh, Xl, nXd4);
    transpose_split_kernel<<<dim3(DMODEL / 32, DMODEL / 32), tb>>>(wq, Wqh, Wql, DMODEL, DMODEL);
    transpose_split_kernel<<<dim3(DMODEL / 32, DMODEL / 32), tb>>>(wk, Wkh, Wkl, DMODEL, DMODEL);
    transpose_split_kernel<<<dim3(DMODEL / 32, DMODEL / 32), tb>>>(wv, Wvh, Wvl, DMODEL, DMODEL);

    // 2. Projections: Q/K/V = X @ W  (B given as W^T [N,K])
    dim3 gp(DMODEL / 128, SEQ / 128);   // (8, 32)
    hmma_gemm_nt<<<gp, 256, GEMM_SMEM>>>(Xh, Xl, Wqh, Wql, Q, DMODEL, DMODEL);
    hmma_gemm_nt<<<gp, 256, GEMM_SMEM>>>(Xh, Xl, Wkh, Wkl, K, DMODEL, DMODEL);
    hmma_gemm_nt<<<gp, 256, GEMM_SMEM>>>(Xh, Xl, Wvh, Wvl, V, DMODEL, DMODEL);

    // 3. Split Q and K for the score GEMM. V stays fp32 (used by gather).
    split_kernel<<<(nXd4 + 255) / 256, 256>>>(Q, Qh, Ql, nXd4);
    split_kernel<<<(nXd4 + 255) / 256, 256>>>(K, Kh, Kl, nXd4);

    // 4. Scores: S = Q @ K^T
    dim3 gs(SEQ / 128, SEQ / 128);      // (32, 32)
    hmma_gemm_nt<<<gs, 256, GEMM_SMEM>>>(Qh, Ql, Kh, Kl, S, DMODEL, SEQ);

    // 5. Softmax(S/32) in place (fp32 p)
    softmax_inplace_kernel<<<SEQ, 256>>>(S);

    // 6. Context: sparse gather out = P @ V (exact fp32 on significant entries)
    pv_gather_kernel<<<SEQ, 256>>>(S, V, out);
}

// round 12
// speedup vs baseline: 1.6932x; 1.0150x over previous
#include <cuda_runtime.h>
#include <cuda_fp16.h>
#include <cstdint>
#include <cstddef>

#define SEQ 4096
#define DMODEL 1024

// ---------------------------------------------------------------------------
// Scratch (allocation-free rule: device globals)
// ---------------------------------------------------------------------------
__device__ __align__(128) float g_Q[(size_t)SEQ * DMODEL];
__device__ __align__(128) float g_K[(size_t)SEQ * DMODEL];
__device__ __align__(128) float g_V[(size_t)SEQ * DMODEL];
__device__ __align__(128) float g_S[(size_t)SEQ * SEQ];   // scores -> softmax in place

__device__ __align__(128) __half g_Xh[(size_t)SEQ * DMODEL];
__device__ __align__(128) __half g_Xl[(size_t)SEQ * DMODEL];
__device__ __align__(128) __half g_Wqh[(size_t)DMODEL * DMODEL];
__device__ __align__(128) __half g_Wql[(size_t)DMODEL * DMODEL];
__device__ __align__(128) __half g_Wkh[(size_t)DMODEL * DMODEL];
__device__ __align__(128) __half g_Wkl[(size_t)DMODEL * DMODEL];
__device__ __align__(128) __half g_Wvh[(size_t)DMODEL * DMODEL];
__device__ __align__(128) __half g_Wvl[(size_t)DMODEL * DMODEL];
__device__ __align__(128) __half g_Qh[(size_t)SEQ * DMODEL];
__device__ __align__(128) __half g_Ql[(size_t)SEQ * DMODEL];
__device__ __align__(128) __half g_Kh[(size_t)SEQ * DMODEL];
__device__ __align__(128) __half g_Kl[(size_t)SEQ * DMODEL];

// ---------------------------------------------------------------------------
// PTX helpers (base PTX only)
// ---------------------------------------------------------------------------
__device__ __forceinline__ uint32_t smem_u32(const void* p) {
    uint32_t a;
    asm("{ .reg .u64 t; cvta.to.shared.u64 t, %1; cvt.u32.u64 %0, t; }"
        : "=r"(a) : "l"(p));
    return a;
}
#define CP_ASYNC16(dst, src) \
    asm volatile("cp.async.cg.shared.global [%0], [%1], 16;" \
                 :: "r"(dst), "l"(src) : "memory")
#define CP_COMMIT() asm volatile("cp.async.commit_group;" ::: "memory")
#define CP_WAIT2()  asm volatile("cp.async.wait_group 2;" ::: "memory")

#define LDSM_X4(r0, r1, r2, r3, addr) \
    asm volatile("ldmatrix.sync.aligned.m8n8.x4.shared.b16 {%0,%1,%2,%3}, [%4];" \
                 : "=r"(r0), "=r"(r1), "=r"(r2), "=r"(r3) : "r"(addr))

#define MMA_F32ACC(d, a, b) \
    asm volatile("mma.sync.aligned.m16n8k16.row.col.f32.f16.f16.f32 " \
                 "{%0,%1,%2,%3}, {%4,%5,%6,%7}, {%8,%9}, {%0,%1,%2,%3};" \
                 : "+f"((d)[0]), "+f"((d)[1]), "+f"((d)[2]), "+f"((d)[3]) \
                 : "r"((a)[0]), "r"((a)[1]), "r"((a)[2]), "r"((a)[3]), \
                   "r"((b)[0]), "r"((b)[1]))

#define MMA_F16ACC(d, a, b) \
    asm volatile("mma.sync.aligned.m16n8k16.row.col.f16.f16.f16.f16 " \
                 "{%0,%1}, {%2,%3,%4,%5}, {%6,%7}, {%0,%1};" \
                 : "+r"((d)[0]), "+r"((d)[1]) \
                 : "r"((a)[0]), "r"((a)[1]), "r"((a)[2]), "r"((a)[3]), \
                   "r"((b)[0]), "r"((b)[1]))

__device__ __forceinline__ uint32_t sw_off(int row, int chunk) {
    uint32_t off = (uint32_t)(row * 128 + chunk * 16);
    return off ^ ((off >> 3) & 0x70);
}

// ---------------------------------------------------------------------------
// HMMA GEMM (fp16 split): pass-major MMA ordering to kill RAW stalls.
//   sweep 1: 16x F32ACC  (hh)   - all distinct acc32
//   sweep 2: 16x F16ACC  (h*l)  - all distinct acc16
//   sweep 3: 16x F16ACC  (l*h)  - same acc16, distance 16 instructions
// Per-accumulator addition order identical to previous rounds (bitwise same).
// CTA 128x128x64, 256 thr, 8 warps (2x4), warp tile 64x32, 3-stage cp.async.
// ---------------------------------------------------------------------------
#define TILE_128B 16384              // 128 rows x 128 bytes
#define STAGE_B (4 * TILE_128B)      // Ah|Al|Bh|Bl = 64KB
#define NSTAGE  3
#define GEMM_SMEM (NSTAGE * STAGE_B) // 196608

__global__ __launch_bounds__(256, 1) void hmma_gemm_nt(
    const __half* __restrict__ Ah, const __half* __restrict__ Al,
    const __half* __restrict__ Bh, const __half* __restrict__ Bl,
    float* __restrict__ C, int Kd, int Nglob)
{
    extern __shared__ char smem[];
    const int tid = threadIdx.x;
    const int wid = tid >> 5;
    const int lane = tid & 31;
    const int warp_m = wid >> 2;
    const int warp_n = wid & 3;
    const int bx = blockIdx.x, by = blockIdx.y;

    const size_t a_row0 = (size_t)by * 128;
    const size_t b_row0 = (size_t)bx * 128;
    const int NKT = Kd / 64;

    const int ld_r  = tid >> 3;
    const int ld_c8 = tid & 7;
    const uint32_t ld_sw = sw_off(ld_r, ld_c8);

    auto load_tile = [&](int s, int kt) {
        char* base = smem + s * STAGE_B;
        const size_t kcol = (size_t)kt * 64 + ld_c8 * 8;
#pragma unroll
        for (int v = 0; v < 4; v++) {
            const __half* src =
                (v == 0) ? Ah : (v == 1) ? Al : (v == 2) ? Bh : Bl;
            const size_t row0 = (v < 2) ? a_row0 : b_row0;
            uint32_t dst0 = smem_u32(base + v * TILE_128B) + ld_sw;
#pragma unroll
            for (int it = 0; it < 4; it++)
                CP_ASYNC16(dst0 + it * 32 * 128,
                           src + (row0 + ld_r + it * 32) * Kd + kcol);
        }
    };

    load_tile(0, 0); CP_COMMIT();
    load_tile(1, 1); CP_COMMIT();
    load_tile(2, 2); CP_COMMIT();

    float acc32[4][4][4];
    uint32_t acc16[4][4][2];
#pragma unroll
    for (int mt = 0; mt < 4; mt++)
#pragma unroll
        for (int nt = 0; nt < 4; nt++) {
#pragma unroll
            for (int c = 0; c < 4; c++) acc32[mt][nt][c] = 0.0f;
            acc16[mt][nt][0] = 0u;
            acc16[mt][nt][1] = 0u;
        }

    const int lm_row = lane & 15;
    const int lm_hi  = lane >> 4;

#pragma unroll 1
    for (int kt = 0; kt < NKT; kt++) {
        CP_WAIT2();
        __syncthreads();
        char* buf = smem + (kt % NSTAGE) * STAGE_B;
        const uint32_t sAh = smem_u32(buf);
        const uint32_t sAl = sAh + TILE_128B;
        const uint32_t sBh = sAh + 2 * TILE_128B;
        const uint32_t sBl = sAh + 3 * TILE_128B;

#pragma unroll
        for (int ks = 0; ks < 4; ks++) {
            const int chunk = ks * 2 + lm_hi;
            uint32_t a_h[4][4], a_l[4][4];
#pragma unroll
            for (int mt = 0; mt < 4; mt++) {
                const int row = warp_m * 64 + mt * 16 + lm_row;
                const uint32_t so = sw_off(row, chunk);
                LDSM_X4(a_h[mt][0], a_h[mt][1], a_h[mt][2], a_h[mt][3], sAh + so);
                LDSM_X4(a_l[mt][0], a_l[mt][1], a_l[mt][2], a_l[mt][3], sAl + so);
            }
            uint32_t b_h[4][2], b_l[4][2];
#pragma unroll
            for (int np = 0; np < 2; np++) {
                const int row = warp_n * 32 + np * 16 + lm_row;
                const uint32_t so = sw_off(row, chunk);
                uint32_t t0, t1, t2, t3;
                LDSM_X4(t0, t1, t2, t3, sBh + so);
                b_h[2 * np][0] = t0;     b_h[2 * np][1] = t2;
                b_h[2 * np + 1][0] = t1; b_h[2 * np + 1][1] = t3;
                LDSM_X4(t0, t1, t2, t3, sBl + so);
                b_l[2 * np][0] = t0;     b_l[2 * np][1] = t2;
                b_l[2 * np + 1][0] = t1; b_l[2 * np + 1][1] = t3;
            }
            // -- sweep 1: hh -> fp32 accumulators (16 independent MMAs) --
#pragma unroll
            for (int mt = 0; mt < 4; mt++)
#pragma unroll
                for (int nb = 0; nb < 4; nb++)
                    MMA_F32ACC(acc32[mt][nb], a_h[mt], b_h[nb]);
            // -- sweep 2: h*l -> fp16 accumulators (16 independent MMAs) --
#pragma unroll
            for (int mt = 0; mt < 4; mt++)
#pragma unroll
                for (int nb = 0; nb < 4; nb++)
                    MMA_F16ACC(acc16[mt][nb], a_h[mt], b_l[nb]);
            // -- sweep 3: l*h -> same fp16 accumulators, RAW distance 16 --
#pragma unroll
            for (int mt = 0; mt < 4; mt++)
#pragma unroll
                for (int nb = 0; nb < 4; nb++)
                    MMA_F16ACC(acc16[mt][nb], a_l[mt], b_h[nb]);
        }
        __syncthreads();
        if (kt + NSTAGE < NKT) load_tile(kt % NSTAGE, kt + NSTAGE);
        CP_COMMIT();
    }

    const int g = lane >> 2;
    const int t2 = (lane & 3) * 2;
#pragma unroll
    for (int mt = 0; mt < 4; mt++) {
        const size_t r0 = a_row0 + warp_m * 64 + mt * 16 + g;
#pragma unroll
        for (int nt = 0; nt < 4; nt++) {
            float2 x0 = __half22float2(
                *reinterpret_cast<__half2*>(&acc16[mt][nt][0]));
            float2 x1 = __half22float2(
                *reinterpret_cast<__half2*>(&acc16[mt][nt][1]));
            const size_t col = b_row0 + warp_n * 32 + nt * 8 + t2;
            *reinterpret_cast<float2*>(&C[r0 * Nglob + col]) =
                make_float2(acc32[mt][nt][0] + x0.x, acc32[mt][nt][1] + x0.y);
            *reinterpret_cast<float2*>(&C[(r0 + 8) * Nglob + col]) =
                make_float2(acc32[mt][nt][2] + x1.x, acc32[mt][nt][3] + x1.y);
        }
    }
}

// ---------------------------------------------------------------------------
// f32 -> (hi, lo) fp16 split helpers
// ---------------------------------------------------------------------------
__device__ __forceinline__ void split1(float x, __half& h, __half& l) {
    h = __float2half_rn(x);
    l = __float2half_rn(x - __half2float(h));
}

__global__ __launch_bounds__(256) void split_kernel(
    const float* __restrict__ in, __half* __restrict__ hi,
    __half* __restrict__ lo, int n4)
{
    int i = blockIdx.x * blockDim.x + threadIdx.x;
    if (i >= n4) return;
    float4 v = reinterpret_cast<const float4*>(in)[i];
    __half h0, h1, h2, h3, l0, l1, l2, l3;
    split1(v.x, h0, l0); split1(v.y, h1, l1);
    split1(v.z, h2, l2); split1(v.w, h3, l3);
    __half2* ph = reinterpret_cast<__half2*>(hi);
    __half2* pl = reinterpret_cast<__half2*>(lo);
    ph[2 * i + 0] = __halves2half2(h0, h1);
    ph[2 * i + 1] = __halves2half2(h2, h3);
    pl[2 * i + 0] = __halves2half2(l0, l1);
    pl[2 * i + 1] = __halves2half2(l2, l3);
}

// transpose + split: in f32 [R, C] -> out hi/lo fp16 [C, R]
__global__ __launch_bounds__(256) void transpose_split_kernel(
    const float* __restrict__ in, __half* __restrict__ oh,
    __half* __restrict__ ol, int R, int C)
{
    __shared__ float tb[32][33];
    const int bx = blockIdx.x * 32;
    const int by = blockIdx.y * 32;
    const int tx = threadIdx.x, ty = threadIdx.y;
#pragma unroll
    for (int j = 0; j < 4; j++)
        tb[ty + 8 * j][tx] = in[(size_t)(by + ty + 8 * j) * C + bx + tx];
    __syncthreads();
#pragma unroll
    for (int j = 0; j < 4; j++) {
        float v = tb[tx][ty + 8 * j];
        __half h, l;
        split1(v, h, l);
        size_t o = (size_t)(bx + ty + 8 * j) * R + by + tx;
        oh[o] = h;
        ol[o] = l;
    }
}

// ---------------------------------------------------------------------------
// Fused scale + softmax over rows of S [SEQ, SEQ], fp32 p written IN PLACE.
// ---------------------------------------------------------------------------
__global__ __launch_bounds__(256) void softmax_inplace_kernel(float* __restrict__ S)
{
    const float scale = 0.03125f;   // 1/sqrt(1024)
    float* row = S + (size_t)blockIdx.x * SEQ;
    const int t = threadIdx.x;

    __shared__ float smax[8];
    __shared__ float ssum[8];

    float4 v[4];
    float m = -1e30f;
#pragma unroll
    for (int i = 0; i < 4; i++) {
        v[i] = *reinterpret_cast<const float4*>(&row[t * 16 + i * 4]);
        v[i].x *= scale; v[i].y *= scale; v[i].z *= scale; v[i].w *= scale;
        m = fmaxf(m, fmaxf(fmaxf(v[i].x, v[i].y), fmaxf(v[i].z, v[i].w)));
    }
#pragma unroll
    for (int o = 16; o > 0; o >>= 1) m = fmaxf(m, __shfl_xor_sync(0xffffffffu, m, o));
    if ((t & 31) == 0) smax[t >> 5] = m;
    __syncthreads();
    m = smax[0];
#pragma unroll
    for (int w = 1; w < 8; w++) m = fmaxf(m, smax[w]);

    float s = 0.0f;
#pragma unroll
    for (int i = 0; i < 4; i++) {
        v[i].x = __expf(v[i].x - m); v[i].y = __expf(v[i].y - m);
        v[i].z = __expf(v[i].z - m); v[i].w = __expf(v[i].w - m);
        s += v[i].x + v[i].y + v[i].z + v[i].w;
    }
#pragma unroll
    for (int o = 16; o > 0; o >>= 1) s += __shfl_xor_sync(0xffffffffu, s, o);
    if ((t & 31) == 0) ssum[t >> 5] = s;
    __syncthreads();
    s = ssum[0];
#pragma unroll
    for (int w = 1; w < 8; w++) s += ssum[w];
    const float inv = 1.0f / s;

#pragma unroll
    for (int i = 0; i < 4; i++) {
        v[i].x *= inv; v[i].y *= inv; v[i].z *= inv; v[i].w *= inv;
        *reinterpret_cast<float4*>(&row[t * 16 + i * 4]) = v[i];
    }
}

// ---------------------------------------------------------------------------
// Sparse PV: out[s,:] = sum_t P[s,t] * V[t,:], restricted to P > 1e-10.
// One block per row; deterministic block-scan compaction (no atomics).
// ---------------------------------------------------------------------------
__global__ __launch_bounds__(256) void pv_gather_kernel(
    const float* __restrict__ P, const float* __restrict__ V,
    float* __restrict__ out)
{
    __shared__ int   s_idx[SEQ];
    __shared__ float s_p[SEQ];
    __shared__ int   warp_base[9];

    const int srow = blockIdx.x;
    const int t = threadIdx.x;
    const float* prow = P + (size_t)srow * SEQ;
    const float THR = 1e-10f;

    int cnt = 0;
#pragma unroll
    for (int i = 0; i < 16; i++)
        if (prow[t + i * 256] > THR) cnt++;

    int pre = cnt;
#pragma unroll
    for (int o = 1; o < 32; o <<= 1) {
        int v = __shfl_up_sync(0xffffffffu, pre, o);
        if ((t & 31) >= o) pre += v;
    }
    if ((t & 31) == 31) warp_base[(t >> 5) + 1] = pre;
    __syncthreads();
    if (t == 0) {
        warp_base[0] = 0;
        for (int w = 1; w <= 8; w++) warp_base[w] += warp_base[w - 1];
    }
    __syncthreads();
    int k = warp_base[t >> 5] + pre - cnt;

#pragma unroll
    for (int i = 0; i < 16; i++) {
        int col = t + i * 256;
        float p = prow[col];
        if (p > THR) { s_idx[k] = col; s_p[k] = p; k++; }
    }
    __syncthreads();

    const int n = warp_base[8];
    float a0 = 0.0f, a1 = 0.0f, a2 = 0.0f, a3 = 0.0f;
    for (int i = 0; i < n; i++) {
        const float p = s_p[i];
        float4 v = *reinterpret_cast<const float4*>(
            &V[(size_t)s_idx[i] * DMODEL + t * 4]);
        a0 = fmaf(p, v.x, a0); a1 = fmaf(p, v.y, a1);
        a2 = fmaf(p, v.z, a2); a3 = fmaf(p, v.w, a3);
    }
    *reinterpret_cast<float4*>(&out[(size_t)srow * DMODEL + t * 4]) =
        make_float4(a0, a1, a2, a3);
}

// ---------------------------------------------------------------------------
extern "C" void kernel_launch(void* const* d_in, const int* in_sizes, int n_in,
                              void* d_out, int out_size)
{
    const float* x  = (const float*)d_in[0];
    const float* wq = (const float*)d_in[1];
    const float* wk = (const float*)d_in[2];
    const float* wv = (const float*)d_in[3];
    float* out = (float*)d_out;

    float *Q, *K, *V, *S;
    __half *Xh, *Xl, *Wqh, *Wql, *Wkh, *Wkl, *Wvh, *Wvl, *Qh, *Ql, *Kh, *Kl;
    cudaGetSymbolAddress((void**)&Q, g_Q);
    cudaGetSymbolAddress((void**)&K, g_K);
    cudaGetSymbolAddress((void**)&V, g_V);
    cudaGetSymbolAddress((void**)&S, g_S);
    cudaGetSymbolAddress((void**)&Xh, g_Xh);   cudaGetSymbolAddress((void**)&Xl, g_Xl);
    cudaGetSymbolAddress((void**)&Wqh, g_Wqh); cudaGetSymbolAddress((void**)&Wql, g_Wql);
    cudaGetSymbolAddress((void**)&Wkh, g_Wkh); cudaGetSymbolAddress((void**)&Wkl, g_Wkl);
    cudaGetSymbolAddress((void**)&Wvh, g_Wvh); cudaGetSymbolAddress((void**)&Wvl, g_Wvl);
    cudaGetSymbolAddress((void**)&Qh, g_Qh);   cudaGetSymbolAddress((void**)&Ql, g_Ql);
    cudaGetSymbolAddress((void**)&Kh, g_Kh);   cudaGetSymbolAddress((void**)&Kl, g_Kl);

    cudaFuncSetAttribute(hmma_gemm_nt,
                         cudaFuncAttributeMaxDynamicSharedMemorySize, GEMM_SMEM);

    const int nXd4 = SEQ * DMODEL / 4;
    dim3 tb(32, 8);

    // 1. Split X; transpose+split weights.
    split_kernel<<<(nXd4 + 255) / 256, 256>>>(x, Xh, Xl, nXd4);
    transpose_split_kernel<<<dim3(DMODEL / 32, DMODEL / 32), tb>>>(wq, Wqh, Wql, DMODEL, DMODEL);
    transpose_split_kernel<<<dim3(DMODEL / 32, DMODEL / 32), tb>>>(wk, Wkh, Wkl, DMODEL, DMODEL);
    transpose_split_kernel<<<dim3(DMODEL / 32, DMODEL / 32), tb>>>(wv, Wvh, Wvl, DMODEL, DMODEL);

    // 2. Projections: Q/K/V = X @ W  (B given as W^T [N,K])
    dim3 gp(DMODEL / 128, SEQ / 128);   // (8, 32)
    hmma_gemm_nt<<<gp, 256, GEMM_SMEM>>>(Xh, Xl, Wqh, Wql, Q, DMODEL, DMODEL);
    hmma_gemm_nt<<<gp, 256, GEMM_SMEM>>>(Xh, Xl, Wkh, Wkl, K, DMODEL, DMODEL);
    hmma_gemm_nt<<<gp, 256, GEMM_SMEM>>>(Xh, Xl, Wvh, Wvl, V, DMODEL, DMODEL);

    // 3. Split Q and K for the score GEMM. V stays fp32 (used by gather).
    split_kernel<<<(nXd4 + 255) / 256, 256>>>(Q, Qh, Ql, nXd4);
    split_kernel<<<(nXd4 + 255) / 256, 256>>>(K, Kh, Kl, nXd4);

    // 4. Scores: S = Q @ K^T
    dim3 gs(SEQ / 128, SEQ / 128);      // (32, 32)
    hmma_gemm_nt<<<gs, 256, GEMM_SMEM>>>(Qh, Ql, Kh, Kl, S, DMODEL, SEQ);

    // 5. Softmax(S/32) in place (fp32 p)
    softmax_inplace_kernel<<<SEQ, 256>>>(S);

    // 6. Context: sparse gather out = P @ V (exact fp32 on significant entries)
    pv_gather_kernel<<<SEQ, 256>>>(S, V, out);
}

// round 14
// speedup vs baseline: 2.2885x; 1.3516x over previous
#include <cuda_runtime.h>
#include <cuda_fp16.h>
#include <cstdint>
#include <cstddef>

#define SEQ 4096
#define DMODEL 1024

// ---------------------------------------------------------------------------
// Scratch (allocation-free rule: device globals)
// ---------------------------------------------------------------------------
__device__ __align__(128) float g_Q[(size_t)SEQ * DMODEL];
__device__ __align__(128) float g_K[(size_t)SEQ * DMODEL];
__device__ __align__(128) float g_V[(size_t)SEQ * DMODEL];
__device__ __align__(128) float g_S[(size_t)SEQ * SEQ];   // raw approx logits

__device__ __align__(128) __half g_Xh[(size_t)SEQ * DMODEL];
__device__ __align__(128) __half g_Xl[(size_t)SEQ * DMODEL];
__device__ __align__(128) __half g_Wqh[(size_t)DMODEL * DMODEL];
__device__ __align__(128) __half g_Wql[(size_t)DMODEL * DMODEL];
__device__ __align__(128) __half g_Wkh[(size_t)DMODEL * DMODEL];
__device__ __align__(128) __half g_Wkl[(size_t)DMODEL * DMODEL];
__device__ __align__(128) __half g_Wvh[(size_t)DMODEL * DMODEL];
__device__ __align__(128) __half g_Wvl[(size_t)DMODEL * DMODEL];
__device__ __align__(128) __half g_Qh[(size_t)SEQ * DMODEL];
__device__ __align__(128) __half g_Kh[(size_t)SEQ * DMODEL];

// ---------------------------------------------------------------------------
// PTX helpers (base PTX only)
// ---------------------------------------------------------------------------
__device__ __forceinline__ uint32_t smem_u32(const void* p) {
    uint32_t a;
    asm("{ .reg .u64 t; cvta.to.shared.u64 t, %1; cvt.u32.u64 %0, t; }"
        : "=r"(a) : "l"(p));
    return a;
}
#define CP_ASYNC16(dst, src) \
    asm volatile("cp.async.cg.shared.global [%0], [%1], 16;" \
                 :: "r"(dst), "l"(src) : "memory")
#define CP_COMMIT() asm volatile("cp.async.commit_group;" ::: "memory")
#define CP_WAIT2()  asm volatile("cp.async.wait_group 2;" ::: "memory")

#define LDSM_X4(r0, r1, r2, r3, addr) \
    asm volatile("ldmatrix.sync.aligned.m8n8.x4.shared.b16 {%0,%1,%2,%3}, [%4];" \
                 : "=r"(r0), "=r"(r1), "=r"(r2), "=r"(r3) : "r"(addr))

#define MMA_F32ACC(d, a, b) \
    asm volatile("mma.sync.aligned.m16n8k16.row.col.f32.f16.f16.f32 " \
                 "{%0,%1,%2,%3}, {%4,%5,%6,%7}, {%8,%9}, {%0,%1,%2,%3};" \
                 : "+f"((d)[0]), "+f"((d)[1]), "+f"((d)[2]), "+f"((d)[3]) \
                 : "r"((a)[0]), "r"((a)[1]), "r"((a)[2]), "r"((a)[3]), \
                   "r"((b)[0]), "r"((b)[1]))

#define MMA_F16ACC(d, a, b) \
    asm volatile("mma.sync.aligned.m16n8k16.row.col.f16.f16.f16.f16 " \
                 "{%0,%1}, {%2,%3,%4,%5}, {%6,%7}, {%0,%1};" \
                 : "+r"((d)[0]), "+r"((d)[1]) \
                 : "r"((a)[0]), "r"((a)[1]), "r"((a)[2]), "r"((a)[3]), \
                   "r"((b)[0]), "r"((b)[1]))

__device__ __forceinline__ uint32_t sw_off(int row, int chunk) {
    uint32_t off = (uint32_t)(row * 128 + chunk * 16);
    return off ^ ((off >> 3) & 0x70);
}

// ---------------------------------------------------------------------------
// HMMA GEMM, 3-pass fp16 split (validated r11/r12) — used for projections.
// CTA 128x128x64, 256 thr, 8 warps (2x4), warp tile 64x32, 3-stage cp.async.
// ---------------------------------------------------------------------------
#define TILE_128B 16384
#define STAGE_B (4 * TILE_128B)      // Ah|Al|Bh|Bl = 64KB
#define NSTAGE  3
#define GEMM_SMEM (NSTAGE * STAGE_B) // 196608

__global__ __launch_bounds__(256, 1) void hmma_gemm_nt(
    const __half* __restrict__ Ah, const __half* __restrict__ Al,
    const __half* __restrict__ Bh, const __half* __restrict__ Bl,
    float* __restrict__ C, int Kd, int Nglob)
{
    extern __shared__ char smem[];
    const int tid = threadIdx.x;
    const int wid = tid >> 5;
    const int lane = tid & 31;
    const int warp_m = wid >> 2;
    const int warp_n = wid & 3;
    const int bx = blockIdx.x, by = blockIdx.y;

    const size_t a_row0 = (size_t)by * 128;
    const size_t b_row0 = (size_t)bx * 128;
    const int NKT = Kd / 64;

    const int ld_r  = tid >> 3;
    const int ld_c8 = tid & 7;
    const uint32_t ld_sw = sw_off(ld_r, ld_c8);

    auto load_tile = [&](int s, int kt) {
        char* base = smem + s * STAGE_B;
        const size_t kcol = (size_t)kt * 64 + ld_c8 * 8;
#pragma unroll
        for (int v = 0; v < 4; v++) {
            const __half* src =
                (v == 0) ? Ah : (v == 1) ? Al : (v == 2) ? Bh : Bl;
            const size_t row0 = (v < 2) ? a_row0 : b_row0;
            uint32_t dst0 = smem_u32(base + v * TILE_128B) + ld_sw;
#pragma unroll
            for (int it = 0; it < 4; it++)
                CP_ASYNC16(dst0 + it * 32 * 128,
                           src + (row0 + ld_r + it * 32) * Kd + kcol);
        }
    };

    load_tile(0, 0); CP_COMMIT();
    load_tile(1, 1); CP_COMMIT();
    load_tile(2, 2); CP_COMMIT();

    float acc32[4][4][4];
    uint32_t acc16[4][4][2];
#pragma unroll
    for (int mt = 0; mt < 4; mt++)
#pragma unroll
        for (int nt = 0; nt < 4; nt++) {
#pragma unroll
            for (int c = 0; c < 4; c++) acc32[mt][nt][c] = 0.0f;
            acc16[mt][nt][0] = 0u;
            acc16[mt][nt][1] = 0u;
        }

    const int lm_row = lane & 15;
    const int lm_hi  = lane >> 4;

#pragma unroll 1
    for (int kt = 0; kt < NKT; kt++) {
        CP_WAIT2();
        __syncthreads();
        char* buf = smem + (kt % NSTAGE) * STAGE_B;
        const uint32_t sAh = smem_u32(buf);
        const uint32_t sAl = sAh + TILE_128B;
        const uint32_t sBh = sAh + 2 * TILE_128B;
        const uint32_t sBl = sAh + 3 * TILE_128B;

#pragma unroll
        for (int ks = 0; ks < 4; ks++) {
            const int chunk = ks * 2 + lm_hi;
            uint32_t a_h[4][4], a_l[4][4];
#pragma unroll
            for (int mt = 0; mt < 4; mt++) {
                const int row = warp_m * 64 + mt * 16 + lm_row;
                const uint32_t so = sw_off(row, chunk);
                LDSM_X4(a_h[mt][0], a_h[mt][1], a_h[mt][2], a_h[mt][3], sAh + so);
                LDSM_X4(a_l[mt][0], a_l[mt][1], a_l[mt][2], a_l[mt][3], sAl + so);
            }
            uint32_t b_h[4][2], b_l[4][2];
#pragma unroll
            for (int np = 0; np < 2; np++) {
                const int row = warp_n * 32 + np * 16 + lm_row;
                const uint32_t so = sw_off(row, chunk);
                uint32_t t0, t1, t2, t3;
                LDSM_X4(t0, t1, t2, t3, sBh + so);
                b_h[2 * np][0] = t0;     b_h[2 * np][1] = t2;
                b_h[2 * np + 1][0] = t1; b_h[2 * np + 1][1] = t3;
                LDSM_X4(t0, t1, t2, t3, sBl + so);
                b_l[2 * np][0] = t0;     b_l[2 * np][1] = t2;
                b_l[2 * np + 1][0] = t1; b_l[2 * np + 1][1] = t3;
            }
#pragma unroll
            for (int mt = 0; mt < 4; mt++)
#pragma unroll
                for (int nb = 0; nb < 4; nb++)
                    MMA_F32ACC(acc32[mt][nb], a_h[mt], b_h[nb]);
#pragma unroll
            for (int mt = 0; mt < 4; mt++)
#pragma unroll
                for (int nb = 0; nb < 4; nb++)
                    MMA_F16ACC(acc16[mt][nb], a_h[mt], b_l[nb]);
#pragma unroll
            for (int mt = 0; mt < 4; mt++)
#pragma unroll
                for (int nb = 0; nb < 4; nb++)
                    MMA_F16ACC(acc16[mt][nb], a_l[mt], b_h[nb]);
        }
        __syncthreads();
        if (kt + NSTAGE < NKT) load_tile(kt % NSTAGE, kt + NSTAGE);
        CP_COMMIT();
    }

    const int g = lane >> 2;
    const int t2 = (lane & 3) * 2;
#pragma unroll
    for (int mt = 0; mt < 4; mt++) {
        const size_t r0 = a_row0 + warp_m * 64 + mt * 16 + g;
#pragma unroll
        for (int nt = 0; nt < 4; nt++) {
            float2 x0 = __half22float2(
                *reinterpret_cast<__half2*>(&acc16[mt][nt][0]));
            float2 x1 = __half22float2(
                *reinterpret_cast<__half2*>(&acc16[mt][nt][1]));
            const size_t col = b_row0 + warp_n * 32 + nt * 8 + t2;
            *reinterpret_cast<float2*>(&C[r0 * Nglob + col]) =
                make_float2(acc32[mt][nt][0] + x0.x, acc32[mt][nt][1] + x0.y);
            *reinterpret_cast<float2*>(&C[(r0 + 8) * Nglob + col]) =
                make_float2(acc32[mt][nt][2] + x1.x, acc32[mt][nt][3] + x1.y);
        }
    }
}

// ---------------------------------------------------------------------------
// HMMA GEMM, 1-pass fp16 (approx) — for the score matrix.
// Same geometry; stage = Ah|Bh = 32KB, 3 stages.
// ---------------------------------------------------------------------------
#define STAGE1_B (2 * TILE_128B)       // 32KB
#define GEMM1_SMEM (NSTAGE * STAGE1_B) // 98304

__global__ __launch_bounds__(256, 1) void hmma_gemm_nt_1p(
    const __half* __restrict__ Ah, const __half* __restrict__ Bh,
    float* __restrict__ C, int Kd, int Nglob)
{
    extern __shared__ char smem[];
    const int tid = threadIdx.x;
    const int wid = tid >> 5;
    const int lane = tid & 31;
    const int warp_m = wid >> 2;
    const int warp_n = wid & 3;
    const int bx = blockIdx.x, by = blockIdx.y;

    const size_t a_row0 = (size_t)by * 128;
    const size_t b_row0 = (size_t)bx * 128;
    const int NKT = Kd / 64;

    const int ld_r  = tid >> 3;
    const int ld_c8 = tid & 7;
    const uint32_t ld_sw = sw_off(ld_r, ld_c8);

    auto load_tile = [&](int s, int kt) {
        char* base = smem + s * STAGE1_B;
        const size_t kcol = (size_t)kt * 64 + ld_c8 * 8;
#pragma unroll
        for (int v = 0; v < 2; v++) {
            const __half* src = (v == 0) ? Ah : Bh;
            const size_t row0 = (v == 0) ? a_row0 : b_row0;
            uint32_t dst0 = smem_u32(base + v * TILE_128B) + ld_sw;
#pragma unroll
            for (int it = 0; it < 4; it++)
                CP_ASYNC16(dst0 + it * 32 * 128,
                           src + (row0 + ld_r + it * 32) * Kd + kcol);
        }
    };

    load_tile(0, 0); CP_COMMIT();
    load_tile(1, 1); CP_COMMIT();
    load_tile(2, 2); CP_COMMIT();

    float acc32[4][4][4];
#pragma unroll
    for (int mt = 0; mt < 4; mt++)
#pragma unroll
        for (int nt = 0; nt < 4; nt++)
#pragma unroll
            for (int c = 0; c < 4; c++) acc32[mt][nt][c] = 0.0f;

    const int lm_row = lane & 15;
    const int lm_hi  = lane >> 4;

#pragma unroll 1
    for (int kt = 0; kt < NKT; kt++) {
        CP_WAIT2();
        __syncthreads();
        char* buf = smem + (kt % NSTAGE) * STAGE1_B;
        const uint32_t sAh = smem_u32(buf);
        const uint32_t sBh = sAh + TILE_128B;

#pragma unroll
        for (int ks = 0; ks < 4; ks++) {
            const int chunk = ks * 2 + lm_hi;
            uint32_t a_h[4][4];
#pragma unroll
            for (int mt = 0; mt < 4; mt++) {
                const int row = warp_m * 64 + mt * 16 + lm_row;
                LDSM_X4(a_h[mt][0], a_h[mt][1], a_h[mt][2], a_h[mt][3],
                        sAh + sw_off(row, chunk));
            }
            uint32_t b_h[4][2];
#pragma unroll
            for (int np = 0; np < 2; np++) {
                const int row = warp_n * 32 + np * 16 + lm_row;
                uint32_t t0, t1, t2, t3;
                LDSM_X4(t0, t1, t2, t3, sBh + sw_off(row, chunk));
                b_h[2 * np][0] = t0;     b_h[2 * np][1] = t2;
                b_h[2 * np + 1][0] = t1; b_h[2 * np + 1][1] = t3;
            }
#pragma unroll
            for (int mt = 0; mt < 4; mt++)
#pragma unroll
                for (int nb = 0; nb < 4; nb++)
                    MMA_F32ACC(acc32[mt][nb], a_h[mt], b_h[nb]);
        }
        __syncthreads();
        if (kt + NSTAGE < NKT) load_tile(kt % NSTAGE, kt + NSTAGE);
        CP_COMMIT();
    }

    const int g = lane >> 2;
    const int t2 = (lane & 3) * 2;
#pragma unroll
    for (int mt = 0; mt < 4; mt++) {
        const size_t r0 = a_row0 + warp_m * 64 + mt * 16 + g;
#pragma unroll
        for (int nt = 0; nt < 4; nt++) {
            const size_t col = b_row0 + warp_n * 32 + nt * 8 + t2;
            *reinterpret_cast<float2*>(&C[r0 * Nglob + col]) =
                make_float2(acc32[mt][nt][0], acc32[mt][nt][1]);
            *reinterpret_cast<float2*>(&C[(r0 + 8) * Nglob + col]) =
                make_float2(acc32[mt][nt][2], acc32[mt][nt][3]);
        }
    }
}

// ---------------------------------------------------------------------------
// f32 -> (hi, lo) fp16 split helpers
// ---------------------------------------------------------------------------
__device__ __forceinline__ void split1(float x, __half& h, __half& l) {
    h = __float2half_rn(x);
    l = __float2half_rn(x - __half2float(h));
}

__global__ __launch_bounds__(256) void split_kernel(
    const float* __restrict__ in, __half* __restrict__ hi,
    __half* __restrict__ lo, int n4)
{
    int i = blockIdx.x * blockDim.x + threadIdx.x;
    if (i >= n4) return;
    float4 v = reinterpret_cast<const float4*>(in)[i];
    __half h0, h1, h2, h3, l0, l1, l2, l3;
    split1(v.x, h0, l0); split1(v.y, h1, l1);
    split1(v.z, h2, l2); split1(v.w, h3, l3);
    __half2* ph = reinterpret_cast<__half2*>(hi);
    __half2* pl = reinterpret_cast<__half2*>(lo);
    ph[2 * i + 0] = __halves2half2(h0, h1);
    ph[2 * i + 1] = __halves2half2(h2, h3);
    pl[2 * i + 0] = __halves2half2(l0, l1);
    pl[2 * i + 1] = __halves2half2(l2, l3);
}

// hi-only conversion (for approx QK operands)
__global__ __launch_bounds__(256) void split_hi_kernel(
    const float* __restrict__ in, __half* __restrict__ hi, int n4)
{
    int i = blockIdx.x * blockDim.x + threadIdx.x;
    if (i >= n4) return;
    float4 v = reinterpret_cast<const float4*>(in)[i];
    __half2* ph = reinterpret_cast<__half2*>(hi);
    ph[2 * i + 0] = __halves2half2(__float2half_rn(v.x), __float2half_rn(v.y));
    ph[2 * i + 1] = __halves2half2(__float2half_rn(v.z), __float2half_rn(v.w));
}

// transpose + split: in f32 [R, C] -> out hi/lo fp16 [C, R]
__global__ __launch_bounds__(256) void transpose_split_kernel(
    const float* __restrict__ in, __half* __restrict__ oh,
    __half* __restrict__ ol, int R, int C)
{
    __shared__ float tb[32][33];
    const int bx = blockIdx.x * 32;
    const int by = blockIdx.y * 32;
    const int tx = threadIdx.x, ty = threadIdx.y;
#pragma unroll
    for (int j = 0; j < 4; j++)
        tb[ty + 8 * j][tx] = in[(size_t)(by + ty + 8 * j) * C + bx + tx];
    __syncthreads();
#pragma unroll
    for (int j = 0; j < 4; j++) {
        float v = tb[tx][ty + 8 * j];
        __half h, l;
        split1(v, h, l);
        size_t o = (size_t)(bx + ty + 8 * j) * R + by + tx;
        oh[o] = h;
        ol[o] = l;
    }
}

// ---------------------------------------------------------------------------
// Fused candidate-softmax-gather:
//   per row: approx max -> candidates (raw band 864 = 27*32; 12-sigma safe)
//   -> exact fp32 logits for candidates -> softmax -> out = sum p * V[t,:]
// All s_idx writes are bounds-guarded (k < MAXC) on every path.
// ---------------------------------------------------------------------------
#define MAXC 2048

__global__ __launch_bounds__(256) void attend_fixup_kernel(
    const float* __restrict__ S, const float* __restrict__ Qf,
    const float* __restrict__ Kf, const float* __restrict__ V,
    float* __restrict__ out)
{
    __shared__ float qrow[DMODEL];
    __shared__ int   s_idx[MAXC];
    __shared__ float s_val[MAXC];
    __shared__ float red[8];
    __shared__ int   warp_base[9];

    const int srow = blockIdx.x;
    const int t = threadIdx.x;
    const int wid = t >> 5, lane = t & 31;
    const float* sr = S + (size_t)srow * SEQ;

    // Q row into smem
    for (int i = t; i < DMODEL; i += 256)
        qrow[i] = Qf[(size_t)srow * DMODEL + i];

    // 1. approx row max (raw logits)
    float m = -1e30f;
#pragma unroll
    for (int i = 0; i < 16; i++) m = fmaxf(m, sr[t + i * 256]);
#pragma unroll
    for (int o = 16; o > 0; o >>= 1) m = fmaxf(m, __shfl_xor_sync(0xffffffffu, m, o));
    if (lane == 0) red[wid] = m;
    __syncthreads();
    m = red[0];
#pragma unroll
    for (int w = 1; w < 8; w++) m = fmaxf(m, red[w]);
    __syncthreads();

    // 2. candidate compaction (band retry; deterministic cap; all writes guarded)
    float band = 864.0f;
    int total = 0;
    for (int attempt = 0; attempt < 2; attempt++) {
        int cnt = 0;
#pragma unroll
        for (int i = 0; i < 16; i++)
            if (sr[t + i * 256] >= m - band) cnt++;
        int pre = cnt;
#pragma unroll
        for (int o = 1; o < 32; o <<= 1) {
            int v = __shfl_up_sync(0xffffffffu, pre, o);
            if (lane >= o) pre += v;
        }
        if (lane == 31) warp_base[wid + 1] = pre;
        __syncthreads();
        if (t == 0) {
            warp_base[0] = 0;
            for (int w = 1; w <= 8; w++) warp_base[w] += warp_base[w - 1];
        }
        __syncthreads();
        total = warp_base[8];
        if (total <= MAXC) {
            int k = warp_base[wid] + pre - cnt;
#pragma unroll
            for (int i = 0; i < 16; i++) {
                int col = t + i * 256;
                if (sr[col] >= m - band) { if (k < MAXC) s_idx[k] = col; k++; }
            }
            break;
        }
        __syncthreads();
        if (attempt == 0) { band = 256.0f; continue; }
        // still too many: deterministic cap in column order
        int k = warp_base[wid] + pre - cnt;
#pragma unroll
        for (int i = 0; i < 16; i++) {
            int col = t + i * 256;
            if (sr[col] >= m - band) { if (k < MAXC) s_idx[k] = col; k++; }
        }
        total = MAXC;
    }
    if (total > MAXC) total = MAXC;
    __syncthreads();

    // 3. exact fp32 scaled logits for candidates (one warp per candidate)
    for (int c = wid; c < total; c += 8) {
        const float* krow = Kf + (size_t)s_idx[c] * DMODEL;
        float acc = 0.0f;
#pragma unroll
        for (int j = 0; j < DMODEL / 32; j++)
            acc = fmaf(qrow[lane + j * 32], krow[lane + j * 32], acc);
#pragma unroll
        for (int o = 16; o > 0; o >>= 1) acc += __shfl_xor_sync(0xffffffffu, acc, o);
        if (lane == 0) s_val[c] = acc * 0.03125f;
    }
    __syncthreads();

    // 4. exact max over candidates
    float mx = -1e30f;
    for (int c = t; c < total; c += 256) mx = fmaxf(mx, s_val[c]);
#pragma unroll
    for (int o = 16; o > 0; o >>= 1) mx = fmaxf(mx, __shfl_xor_sync(0xffffffffu, mx, o));
    if (lane == 0) red[wid] = mx;
    __syncthreads();
    mx = red[0];
#pragma unroll
    for (int w = 1; w < 8; w++) mx = fmaxf(mx, red[w]);
    __syncthreads();

    // 5. exp + sum
    float ssum = 0.0f;
    for (int c = t; c < total; c += 256) {
        float p = __expf(s_val[c] - mx);
        s_val[c] = p;
        ssum += p;
    }
#pragma unroll
    for (int o = 16; o > 0; o >>= 1) ssum += __shfl_xor_sync(0xffffffffu, ssum, o);
    if (lane == 0) red[wid] = ssum;
    __syncthreads();
    ssum = red[0];
#pragma unroll
    for (int w = 1; w < 8; w++) ssum += red[w];
    const float inv = 1.0f / ssum;
    __syncthreads();

    // 6. out[srow,:] = sum p * V[t,:]   (each thread: 4 dims)
    float a0 = 0.0f, a1 = 0.0f, a2 = 0.0f, a3 = 0.0f;
    for (int c = 0; c < total; c++) {
        const float p = s_val[c] * inv;
        float4 v = *reinterpret_cast<const float4*>(
            &V[(size_t)s_idx[c] * DMODEL + t * 4]);
        a0 = fmaf(p, v.x, a0); a1 = fmaf(p, v.y, a1);
        a2 = fmaf(p, v.z, a2); a3 = fmaf(p, v.w, a3);
    }
    *reinterpret_cast<float4*>(&out[(size_t)srow * DMODEL + t * 4]) =
        make_float4(a0, a1, a2, a3);
}

// ---------------------------------------------------------------------------
extern "C" void kernel_launch(void* const* d_in, const int* in_sizes, int n_in,
                              void* d_out, int out_size)
{
    const float* x  = (const float*)d_in[0];
    const float* wq = (const float*)d_in[1];
    const float* wk = (const float*)d_in[2];
    const float* wv = (const float*)d_in[3];
    float* out = (float*)d_out;

    float *Q, *K, *V, *S;
    __half *Xh, *Xl, *Wqh, *Wql, *Wkh, *Wkl, *Wvh, *Wvl, *Qh, *Kh;
    cudaGetSymbolAddress((void**)&Q, g_Q);
    cudaGetSymbolAddress((void**)&K, g_K);
    cudaGetSymbolAddress((void**)&V, g_V);
    cudaGetSymbolAddress((void**)&S, g_S);
    cudaGetSymbolAddress((void**)&Xh, g_Xh);   cudaGetSymbolAddress((void**)&Xl, g_Xl);
    cudaGetSymbolAddress((void**)&Wqh, g_Wqh); cudaGetSymbolAddress((void**)&Wql, g_Wql);
    cudaGetSymbolAddress((void**)&Wkh, g_Wkh); cudaGetSymbolAddress((void**)&Wkl, g_Wkl);
    cudaGetSymbolAddress((void**)&Wvh, g_Wvh); cudaGetSymbolAddress((void**)&Wvl, g_Wvl);
    cudaGetSymbolAddress((void**)&Qh, g_Qh);   cudaGetSymbolAddress((void**)&Kh, g_Kh);

    cudaFuncSetAttribute(hmma_gemm_nt,
                         cudaFuncAttributeMaxDynamicSharedMemorySize, GEMM_SMEM);
    cudaFuncSetAttribute(hmma_gemm_nt_1p,
                         cudaFuncAttributeMaxDynamicSharedMemorySize, GEMM1_SMEM);

    const int nXd4 = SEQ * DMODEL / 4;
    dim3 tb(32, 8);

    // 1. Split X; transpose+split weights.
    split_kernel<<<(nXd4 + 255) / 256, 256>>>(x, Xh, Xl, nXd4);
    transpose_split_kernel<<<dim3(DMODEL / 32, DMODEL / 32), tb>>>(wq, Wqh, Wql, DMODEL, DMODEL);
    transpose_split_kernel<<<dim3(DMODEL / 32, DMODEL / 32), tb>>>(wk, Wkh, Wkl, DMODEL, DMODEL);
    transpose_split_kernel<<<dim3(DMODEL / 32, DMODEL / 32), tb>>>(wv, Wvh, Wvl, DMODEL, DMODEL);

    // 2. Projections (3-pass, accurate)
    dim3 gp(DMODEL / 128, SEQ / 128);   // (8, 32)
    hmma_gemm_nt<<<gp, 256, GEMM_SMEM>>>(Xh, Xl, Wqh, Wql, Q, DMODEL, DMODEL);
    hmma_gemm_nt<<<gp, 256, GEMM_SMEM>>>(Xh, Xl, Wkh, Wkl, K, DMODEL, DMODEL);
    hmma_gemm_nt<<<gp, 256, GEMM_SMEM>>>(Xh, Xl, Wvh, Wvl, V, DMODEL, DMODEL);

    // 3. hi-only fp16 Q, K for the approximate score GEMM.
    split_hi_kernel<<<(nXd4 + 255) / 256, 256>>>(Q, Qh, nXd4);
    split_hi_kernel<<<(nXd4 + 255) / 256, 256>>>(K, Kh, nXd4);

    // 4. Approx scores: S = Qh @ Kh^T (1 pass)
    dim3 gs(SEQ / 128, SEQ / 128);      // (32, 32)
    hmma_gemm_nt_1p<<<gs, 256, GEMM1_SMEM>>>(Qh, Kh, S, DMODEL, SEQ);

    // 5. Candidates -> exact fp32 logits -> softmax -> gather V
    attend_fixup_kernel<<<SEQ, 256>>>(S, Q, K, V, out);
}